// round 9
// baseline (speedup 1.0000x reference)
#include <cuda_runtime.h>
#include <cuda_bf16.h>
#include <math.h>

#define NN 50000
#define EE 500000
#define GG 256
#define DD 64
#define LL 3
#define NT_EDGE ((EE + 127) / 128)

// ------------------------------------------------------------------ globals
__device__ float    g_h[NN * DD];
__device__ unsigned g_ea[(size_t)EE * 32];      // bf16x2 words
__device__ float    g_Ar[NN * DD];
__device__ float    g_Ac[NN * DD];
__device__ float    g_Br[NN * DD];
__device__ float    g_hnew[NN * DD];
__device__ double   g_stats[2 * DD];
__device__ float    g_ab[2 * DD];
__device__ float    g_pool[GG * DD];
__device__ float    g_cnt[GG];
__device__ float    g_cf[GG * 16];

__device__ unsigned g_wbond[2][64 * 36];
__device__ unsigned g_wpre[LL][2][192 * 36];
__device__ unsigned g_wedge[LL][4][2][64 * 36];
__device__ float    g_bpre[LL][192];

__device__ __forceinline__ float sp_f(float x) {
    return x > 15.f ? x : __logf(1.f + __expf(x));
}
__device__ __forceinline__ int clampi(int v, int hi) {
    return v < 0 ? 0 : (v >= hi ? hi - 1 : v);
}
__device__ __forceinline__ unsigned pack2(float x, float y) {
    __nv_bfloat162 h = __floats2bfloat162_rn(x, y);
    return *reinterpret_cast<unsigned*>(&h);
}
__device__ __forceinline__ void red2(float* a, float x, float y) {
    asm volatile("red.global.add.v2.f32 [%0], {%1,%2};" :: "l"(a), "f"(x), "f"(y) : "memory");
}
__device__ __forceinline__ void mma_bf16(float& c0, float& c1, float& c2, float& c3,
                                         unsigned a0, unsigned a1, unsigned a2, unsigned a3,
                                         unsigned b0, unsigned b1) {
    asm volatile("mma.sync.aligned.m16n8k16.row.col.f32.bf16.bf16.f32 "
                 "{%0,%1,%2,%3}, {%4,%5,%6,%7}, {%8,%9}, {%0,%1,%2,%3};\n"
                 : "+f"(c0), "+f"(c1), "+f"(c2), "+f"(c3)
                 : "r"(a0), "r"(a1), "r"(a2), "r"(a3), "r"(b0), "r"(b1));
}

template<int K0, int NT>
__device__ __forceinline__ void mma_tiles(const unsigned* sA, const unsigned* sWhi,
                                          const unsigned* sWlo, float acc[][NT][4],
                                          int wm, int wcol0, int gid, int tig) {
#pragma unroll
    for (int k0 = 0; k0 < K0; k0++) {
        unsigned a[2][4];
#pragma unroll
        for (int mt = 0; mt < 2; mt++) {
            const unsigned* base = &sA[(wm * 32 + mt * 16 + gid) * 36 + k0 * 8 + tig];
            a[mt][0] = base[0];
            a[mt][1] = base[8 * 36];
            a[mt][2] = base[4];
            a[mt][3] = base[8 * 36 + 4];
        }
#pragma unroll
        for (int nt = 0; nt < NT; nt++) {
            int off = (wcol0 + nt * 8 + gid) * 36 + k0 * 8 + tig;
            unsigned bh0 = sWhi[off], bh1 = sWhi[off + 4];
            unsigned bl0 = sWlo[off], bl1 = sWlo[off + 4];
#pragma unroll
            for (int mt = 0; mt < 2; mt++) {
                mma_bf16(acc[mt][nt][0], acc[mt][nt][1], acc[mt][nt][2], acc[mt][nt][3],
                         a[mt][0], a[mt][1], a[mt][2], a[mt][3], bh0, bh1);
                mma_bf16(acc[mt][nt][0], acc[mt][nt][1], acc[mt][nt][2], acc[mt][nt][3],
                         a[mt][0], a[mt][1], a[mt][2], a[mt][3], bl0, bl1);
            }
        }
    }
}

// ------------------------------------------------------------------ one-time weight conversion
__global__ void k_cvt_all(const float* eu_W1, const float* eu_b1,
                          const float* nu_W1, const float* nu_b1,
                          const float* eu_W2, const float* nu_W2,
                          const float* W_bond) {
    int b = blockIdx.x, tid = threadIdx.x;
    const float* src; unsigned *dhi, *dlo; int ncoff = 0, validK = 64;
    if (b == 0) {
        src = W_bond; validK = 41;
        dhi = g_wbond[0]; dlo = g_wbond[1];
        for (int idx = tid; idx < LL * 192; idx += 256) {
            int i = idx / 192, n = idx % 192;
            float v = 0.f;
            if (n < 64)        v = eu_b1[i * 64 + n];
            else if (n >= 128) v = nu_b1[i * 64 + (n - 128)];
            g_bpre[i][n] = v;
        }
    } else {
        int i = (b - 1) / 7, j = (b - 1) % 7;
        const float* euW1 = eu_W1 + (size_t)i * 12288;
        const float* nuW1 = nu_W1 + (size_t)i * 8192;
        switch (j) {
            case 0: src = euW1;            dhi = g_wpre[i][0]; dlo = g_wpre[i][1]; ncoff = 0;   break;
            case 1: src = euW1 + 4096;     dhi = g_wpre[i][0]; dlo = g_wpre[i][1]; ncoff = 64;  break;
            case 2: src = nuW1;            dhi = g_wpre[i][0]; dlo = g_wpre[i][1]; ncoff = 128; break;
            case 3: src = euW1 + 8192;     dhi = g_wedge[i][0][0]; dlo = g_wedge[i][0][1]; break;
            case 4: src = eu_W2 + (size_t)i * 4096; dhi = g_wedge[i][1][0]; dlo = g_wedge[i][1][1]; break;
            case 5: src = nuW1 + 4096;     dhi = g_wedge[i][2][0]; dlo = g_wedge[i][2][1]; break;
            default: src = nu_W2 + (size_t)i * 4096; dhi = g_wedge[i][3][0]; dlo = g_wedge[i][3][1]; break;
        }
    }
    __nv_bfloat16* hhi = reinterpret_cast<__nv_bfloat16*>(dhi);
    __nv_bfloat16* hlo = reinterpret_cast<__nv_bfloat16*>(dlo);
    for (int idx = tid; idx < 4096; idx += 256) {
        int k = idx >> 6, n = idx & 63;
        float w = (k < validK) ? src[k * 64 + n] : 0.f;
        __nv_bfloat16 hi = __float2bfloat16(w);
        float lo = w - __bfloat162float(hi);
        hhi[(size_t)(n + ncoff) * 72 + k] = hi;
        hlo[(size_t)(n + ncoff) * 72 + k] = __float2bfloat16(lo);
    }
}

// ------------------------------------------------------------------ small kernels
__global__ void k_charge(const float* charge, const float* Wc, const float* bc) {
    int i = blockIdx.x * 256 + threadIdx.x;
    if (i < GG * 16) g_cf[i] = charge[i >> 4] * Wc[i & 15] + bc[i & 15];
    if (i < GG * DD) g_pool[i] = 0.f;
    if (i < GG) g_cnt[i] = 0.f;
}

template<int K, int LDA>
__device__ __forceinline__ void tile_gemm(const float* sA, const float* sW,
                                          float acc[4][4], int tx, int ty) {
#pragma unroll 4
    for (int k = 0; k < K; k += 4) {
        float a[4][4];
#pragma unroll
        for (int i = 0; i < 4; i++)
            *reinterpret_cast<float4*>(a[i]) =
                *reinterpret_cast<const float4*>(&sA[(ty * 4 + i) * LDA + k]);
#pragma unroll
        for (int kk = 0; kk < 4; kk++) {
            float4 b = *reinterpret_cast<const float4*>(&sW[(k + kk) * 64 + tx * 4]);
#pragma unroll
            for (int i = 0; i < 4; i++) {
                acc[i][0] = fmaf(a[i][kk], b.x, acc[i][0]);
                acc[i][1] = fmaf(a[i][kk], b.y, acc[i][1]);
                acc[i][2] = fmaf(a[i][kk], b.z, acc[i][2]);
                acc[i][3] = fmaf(a[i][kk], b.w, acc[i][3]);
            }
        }
    }
}

__global__ __launch_bounds__(256) void k_embed_nodes(
    const float* x, const int* batch, const float* W, const float* b) {
    __shared__ float sW[56 * 64];
    __shared__ float sA[64 * 60];
    __shared__ float sB[64];
    int tid = threadIdx.x, n0 = blockIdx.x * 64;
    int tx = tid & 15, ty = tid >> 4;
    if (tid < 64) sB[tid] = b[tid];
    float acc[4][4] = {};
#pragma unroll 1
    for (int c = 0; c < 2; c++) {
        int k0 = c * 56;
        __syncthreads();
        for (int idx = tid; idx < 56 * 64; idx += 256) {
            int k = k0 + (idx >> 6);
            sW[idx] = (k < 108) ? W[k * 64 + (idx & 63)] : 0.f;
        }
        for (int idx = tid; idx < 64 * 56; idx += 256) {
            int n = idx / 56, kk = idx - n * 56;
            int k = k0 + kk;
            int nn = n0 + n; if (nn >= NN) nn = NN - 1;
            float v;
            if (k < 92)       v = x[(size_t)nn * 92 + k];
            else if (k < 108) v = g_cf[clampi(batch[nn], GG) * 16 + (k - 92)];
            else              v = 0.f;
            sA[n * 60 + kk] = v;
        }
        __syncthreads();
        tile_gemm<56, 60>(sA, sW, acc, tx, ty);
    }
#pragma unroll
    for (int i = 0; i < 4; i++) {
        int n = n0 + ty * 4 + i;
        if (n < NN) {
            float4 v = make_float4(acc[i][0] + sB[tx*4],   acc[i][1] + sB[tx*4+1],
                                   acc[i][2] + sB[tx*4+2], acc[i][3] + sB[tx*4+3]);
            *reinterpret_cast<float4*>(&g_h[n * 64 + tx * 4]) = v;
        }
    }
}

// ------------------------------------------------------------------ edge embedding (non-persistent)
__global__ __launch_bounds__(256) void k_embed_edges_mma(const float* ea, const float* b) {
    __shared__ unsigned sA[128 * 36];
    __shared__ unsigned sW[2 * 64 * 36];
    int tid = threadIdx.x, e0 = blockIdx.x * 128;
    int warp = tid >> 5, lane = tid & 31;
    int wm = warp >> 1, wn = warp & 1;
    int gid = lane >> 2, tig = lane & 3;

    {
        const uint4* src = reinterpret_cast<const uint4*>(g_wbond[0]);
        uint4* dst = reinterpret_cast<uint4*>(sW);
        for (int idx = tid; idx < 2 * 64 * 36 / 4; idx += 256) dst[idx] = src[idx];
    }
    for (int idx = tid; idx < 128 * 24; idx += 256) {
        int er = idx / 24, kw = idx - er * 24;
        int k = kw * 2;
        int e = e0 + er; if (e >= EE) e = EE - 1;
        float v0 = (k < 41)     ? ea[(size_t)e * 41 + k]     : 0.f;
        float v1 = (k + 1 < 41) ? ea[(size_t)e * 41 + k + 1] : 0.f;
        sA[er * 36 + kw] = pack2(v0, v1);
    }
    __syncthreads();

    float acc[2][4][4];
#pragma unroll
    for (int mt = 0; mt < 2; mt++)
#pragma unroll
        for (int nt = 0; nt < 4; nt++) {
            float2 bv = *reinterpret_cast<const float2*>(&b[wn * 32 + nt * 8 + tig * 2]);
            acc[mt][nt][0] = bv.x; acc[mt][nt][1] = bv.y;
            acc[mt][nt][2] = bv.x; acc[mt][nt][3] = bv.y;
        }
    mma_tiles<3, 4>(sA, sW, sW + 64 * 36, acc, wm, wn * 32, gid, tig);
#pragma unroll
    for (int mt = 0; mt < 2; mt++)
#pragma unroll
        for (int nt = 0; nt < 4; nt++) {
            int row = wm * 32 + mt * 16 + gid;
            int cw = wn * 16 + nt * 4 + tig;
            int e = e0 + row;
            if (e < EE)     g_ea[(size_t)e * 32 + cw]       = pack2(acc[mt][nt][0], acc[mt][nt][1]);
            if (e + 8 < EE) g_ea[(size_t)(e + 8) * 32 + cw] = pack2(acc[mt][nt][2], acc[mt][nt][3]);
        }
}

// ------------------------------------------------------------------ fused precompute (Ar|Ac|Br)
__global__ __launch_bounds__(256) void k_precompute(int layer) {
    extern __shared__ unsigned dyn[];
    unsigned* sA = dyn;
    unsigned* sW = dyn + 128 * 36;
    int tid = threadIdx.x, n0 = blockIdx.x * 128;
    int warp = tid >> 5, lane = tid & 31;
    int wm = warp >> 1, wn = warp & 1;
    int gid = lane >> 2, tig = lane & 3;
    if (blockIdx.x == 0 && tid < 128) g_stats[tid] = 0.0;

    {
        const uint4* src = reinterpret_cast<const uint4*>(g_wpre[layer][0]);
        uint4* dst = reinterpret_cast<uint4*>(sW);
        for (int idx = tid; idx < 2 * 192 * 36 / 4; idx += 256) dst[idx] = src[idx];
    }
    for (int idx = tid; idx < 128 * 32; idx += 256) {
        int nr = idx >> 5, cw = idx & 31;
        int n = n0 + nr;
        if (n < NN) {
            float2 v = *reinterpret_cast<const float2*>(&g_h[(size_t)n * 64 + cw * 2]);
            sA[nr * 36 + cw] = pack2(v.x, v.y);
            *reinterpret_cast<float2*>(&g_hnew[(size_t)n * 64 + cw * 2]) = make_float2(0.f, 0.f);
        } else sA[nr * 36 + cw] = 0u;
    }
    __syncthreads();

    float acc[2][12][4];
#pragma unroll
    for (int mt = 0; mt < 2; mt++)
#pragma unroll
        for (int nt = 0; nt < 12; nt++) {
            int nc = wn * 96 + nt * 8 + tig * 2;
            float2 bv = *reinterpret_cast<const float2*>(&g_bpre[layer][nc]);
            acc[mt][nt][0] = bv.x; acc[mt][nt][1] = bv.y;
            acc[mt][nt][2] = bv.x; acc[mt][nt][3] = bv.y;
        }
    mma_tiles<4, 12>(sA, sW, sW + 192 * 36, acc, wm, wn * 96, gid, tig);
#pragma unroll
    for (int mt = 0; mt < 2; mt++)
#pragma unroll
        for (int nt = 0; nt < 12; nt++) {
            int nc = wn * 96 + nt * 8 + tig * 2;
            float* O = nc < 64 ? g_Ar : (nc < 128 ? g_Ac : g_Br);
            int col = nc & 63;
            int row = wm * 32 + mt * 16 + gid;
            int n = n0 + row;
            if (n < NN)
                *reinterpret_cast<float2*>(&O[(size_t)n * 64 + col]) =
                    make_float2(acc[mt][nt][0], acc[mt][nt][1]);
            if (n + 8 < NN)
                *reinterpret_cast<float2*>(&O[(size_t)(n + 8) * 64 + col]) =
                    make_float2(acc[mt][nt][2], acc[mt][nt][3]);
        }
}

// ------------------------------------------------------------------ fused edge pipeline
// persistent, ping-pong buffers, register-resident indices, 4 syncs/tile
__global__ __launch_bounds__(256, 2) void k_edge(const int* eidx, int layer,
                                                 const float* b2, const float* b4,
                                                 int store_ea) {
    extern __shared__ unsigned dyn[];
    unsigned* s0 = dyn;                    // 128*36
    unsigned* s1 = dyn + 128 * 36;         // 128*36
    unsigned* sW = dyn + 2 * 128 * 36;     // 4 stages * (hi 2304 + lo 2304)

    int tid = threadIdx.x;
    int warp = tid >> 5, lane = tid & 31;
    int wm = warp >> 1, wn = warp & 1;
    int gid = lane >> 2, tig = lane & 3;

    float2 bias2[4], bias4[4];
#pragma unroll
    for (int nt = 0; nt < 4; nt++) {
        bias2[nt] = *reinterpret_cast<const float2*>(&b2[wn * 32 + nt * 8 + tig * 2]);
        bias4[nt] = *reinterpret_cast<const float2*>(&b4[wn * 32 + nt * 8 + tig * 2]);
    }
    {
        const uint4* src = reinterpret_cast<const uint4*>(&g_wedge[layer][0][0][0]);
        uint4* dst = reinterpret_cast<uint4*>(sW);
        for (int idx = tid; idx < 4 * 2 * 2304 / 4; idx += 256) dst[idx] = src[idx];
    }
    const unsigned* W1h = sW;
    const unsigned* W2h = sW + 4608;
    const unsigned* W3h = sW + 9216;
    const unsigned* W4h = sW + 13824;

    for (int t = blockIdx.x; t < NT_EDGE; t += gridDim.x) {
        int e0 = t * 128;
        // per-thread register indices (no smem, no WAR hazard)
        int r_[2][2], c_[2][2];
#pragma unroll
        for (int mt = 0; mt < 2; mt++) {
            int row = wm * 32 + mt * 16 + gid;
            int ea0 = e0 + row;     if (ea0 >= EE) ea0 = EE - 1;
            int ea1 = e0 + row + 8; if (ea1 >= EE) ea1 = EE - 1;
            r_[mt][0] = clampi(eidx[ea0], NN); c_[mt][0] = clampi(eidx[EE + ea0], NN);
            r_[mt][1] = clampi(eidx[ea1], NN); c_[mt][1] = clampi(eidx[EE + ea1], NN);
        }
        for (int idx = tid; idx < 128 * 32; idx += 256) {
            int er = idx >> 5, cw = idx & 31;
            int e = e0 + er; if (e >= EE) e = EE - 1;
            s0[er * 36 + cw] = g_ea[(size_t)e * 32 + cw];
        }
        __syncthreads();                                        // (1)

        float acc[2][4][4];

        // ---- stage 1: t = sp(s0 @ W1c + Ar[row] + Ac[col]) -> s1
#pragma unroll
        for (int mt = 0; mt < 2; mt++)
#pragma unroll
            for (int nt = 0; nt < 4; nt++) {
                int col = wn * 32 + nt * 8 + tig * 2;
                float2 a0 = *reinterpret_cast<const float2*>(&g_Ar[(size_t)r_[mt][0] * 64 + col]);
                float2 q0 = *reinterpret_cast<const float2*>(&g_Ac[(size_t)c_[mt][0] * 64 + col]);
                float2 a1 = *reinterpret_cast<const float2*>(&g_Ar[(size_t)r_[mt][1] * 64 + col]);
                float2 q1 = *reinterpret_cast<const float2*>(&g_Ac[(size_t)c_[mt][1] * 64 + col]);
                acc[mt][nt][0] = a0.x + q0.x; acc[mt][nt][1] = a0.y + q0.y;
                acc[mt][nt][2] = a1.x + q1.x; acc[mt][nt][3] = a1.y + q1.y;
            }
        mma_tiles<4, 4>(s0, W1h, W1h + 2304, acc, wm, wn * 32, gid, tig);
#pragma unroll
        for (int mt = 0; mt < 2; mt++)
#pragma unroll
            for (int nt = 0; nt < 4; nt++) {
                int row = wm * 32 + mt * 16 + gid;
                int cw = wn * 16 + nt * 4 + tig;
                s1[row * 36 + cw]       = pack2(sp_f(acc[mt][nt][0]), sp_f(acc[mt][nt][1]));
                s1[(row + 8) * 36 + cw] = pack2(sp_f(acc[mt][nt][2]), sp_f(acc[mt][nt][3]));
            }
        __syncthreads();                                        // (2)

        // ---- stage 2: ea_new = s1 @ W2 + b2 -> s0 (+gmem)
#pragma unroll
        for (int mt = 0; mt < 2; mt++)
#pragma unroll
            for (int nt = 0; nt < 4; nt++) {
                acc[mt][nt][0] = bias2[nt].x; acc[mt][nt][1] = bias2[nt].y;
                acc[mt][nt][2] = bias2[nt].x; acc[mt][nt][3] = bias2[nt].y;
            }
        mma_tiles<4, 4>(s1, W2h, W2h + 2304, acc, wm, wn * 32, gid, tig);
#pragma unroll
        for (int mt = 0; mt < 2; mt++)
#pragma unroll
            for (int nt = 0; nt < 4; nt++) {
                int row = wm * 32 + mt * 16 + gid;
                int cw = wn * 16 + nt * 4 + tig;
                unsigned p0 = pack2(acc[mt][nt][0], acc[mt][nt][1]);
                unsigned p1 = pack2(acc[mt][nt][2], acc[mt][nt][3]);
                s0[row * 36 + cw]       = p0;
                s0[(row + 8) * 36 + cw] = p1;
                if (store_ea) {
                    int e = e0 + row;
                    if (e < EE)     g_ea[(size_t)e * 32 + cw]       = p0;
                    if (e + 8 < EE) g_ea[(size_t)(e + 8) * 32 + cw] = p1;
                }
            }
        __syncthreads();                                        // (3)

        // ---- stage 3: u = sp(s0 @ W3 + Br[row]) -> s1
#pragma unroll
        for (int mt = 0; mt < 2; mt++)
#pragma unroll
            for (int nt = 0; nt < 4; nt++) {
                int col = wn * 32 + nt * 8 + tig * 2;
                float2 v0 = *reinterpret_cast<const float2*>(&g_Br[(size_t)r_[mt][0] * 64 + col]);
                float2 v1 = *reinterpret_cast<const float2*>(&g_Br[(size_t)r_[mt][1] * 64 + col]);
                acc[mt][nt][0] = v0.x; acc[mt][nt][1] = v0.y;
                acc[mt][nt][2] = v1.x; acc[mt][nt][3] = v1.y;
            }
        mma_tiles<4, 4>(s0, W3h, W3h + 2304, acc, wm, wn * 32, gid, tig);
#pragma unroll
        for (int mt = 0; mt < 2; mt++)
#pragma unroll
            for (int nt = 0; nt < 4; nt++) {
                int row = wm * 32 + mt * 16 + gid;
                int cw = wn * 16 + nt * 4 + tig;
                s1[row * 36 + cw]       = pack2(sp_f(acc[mt][nt][0]), sp_f(acc[mt][nt][1]));
                s1[(row + 8) * 36 + cw] = pack2(sp_f(acc[mt][nt][2]), sp_f(acc[mt][nt][3]));
            }
        __syncthreads();                                        // (4)

        // ---- stage 4: msg = s1 @ W4 + b4 -> red scatter (no trailing sync;
        //      next tile touches only s0, protected by sync (1))
#pragma unroll
        for (int mt = 0; mt < 2; mt++)
#pragma unroll
            for (int nt = 0; nt < 4; nt++) {
                acc[mt][nt][0] = bias4[nt].x; acc[mt][nt][1] = bias4[nt].y;
                acc[mt][nt][2] = bias4[nt].x; acc[mt][nt][3] = bias4[nt].y;
            }
        mma_tiles<4, 4>(s1, W4h, W4h + 2304, acc, wm, wn * 32, gid, tig);
#pragma unroll
        for (int mt = 0; mt < 2; mt++)
#pragma unroll
            for (int nt = 0; nt < 4; nt++) {
                int row = wm * 32 + mt * 16 + gid;
                int col = wn * 32 + nt * 8 + tig * 2;
                int e = e0 + row;
                if (e < EE)
                    red2(&g_hnew[(size_t)c_[mt][0] * 64 + col], acc[mt][nt][0], acc[mt][nt][1]);
                if (e + 8 < EE)
                    red2(&g_hnew[(size_t)c_[mt][1] * 64 + col], acc[mt][nt][2], acc[mt][nt][3]);
            }
    }
}

// ------------------------------------------------------------------ tail kernels
__global__ void k_stats() {
    int c = threadIdx.x & 63, rr = threadIdx.x >> 6;
    double s = 0.0, s2 = 0.0;
    for (int n = blockIdx.x * 4 + rr; n < NN; n += gridDim.x * 4) {
        float v = g_hnew[n * 64 + c];
        s += v; s2 += (double)v * v;
    }
    __shared__ double sh[8][64];
    sh[rr][c] = s; sh[4 + rr][c] = s2;
    __syncthreads();
    if (rr == 0) {
        atomicAdd(&g_stats[c],      sh[0][c] + sh[1][c] + sh[2][c] + sh[3][c]);
        atomicAdd(&g_stats[64 + c], sh[4][c] + sh[5][c] + sh[6][c] + sh[7][c]);
    }
}

__global__ void k_finalize(const float* gamma, const float* beta) {
    int j = threadIdx.x;
    double mu = g_stats[j] / (double)NN;
    double var = g_stats[64 + j] / (double)NN - mu * mu;
    float a = rsqrtf((float)var + 1e-5f) * gamma[j];
    g_ab[j] = a;
    g_ab[64 + j] = beta[j] - (float)mu * a;
}

// BN-apply + softplus + residual; on last layer also fused global mean pool
__global__ void k_update(const int* batch, int do_pool) {
    int idx = blockIdx.x * 256 + threadIdx.x;
    int j = idx & 63;
    float v = g_hnew[idx] * g_ab[j] + g_ab[64 + j];
    float h = sp_f(v) + g_h[idx];
    g_h[idx] = h;
    if (do_pool) {
        int b = clampi(batch[idx >> 6], GG);
        atomicAdd(&g_pool[b * 64 + j], h);
        if (j == 0) atomicAdd(&g_cnt[b], 1.f);
    }
}

__global__ void k_predict(const float* W1, const float* b1,
                          const float* W2, const float* b2,
                          const float* W3, const float* b3, float* out) {
    __shared__ float gr[64], z1[128], z2[128];
    __shared__ float red[4];
    int g = blockIdx.x, t = threadIdx.x;
    if (t < 64) gr[t] = g_pool[g * 64 + t] / fmaxf(g_cnt[g], 1.f);
    __syncthreads();
    float acc = b1[t];
    for (int k = 0; k < 64; k++) acc = fmaf(gr[k], W1[k * 128 + t], acc);
    z1[t] = sp_f(acc);
    __syncthreads();
    acc = b2[t];
    for (int k = 0; k < 128; k++) acc = fmaf(z1[k], W2[k * 128 + t], acc);
    z2[t] = sp_f(acc);
    __syncthreads();
    float v = z2[t] * W3[t];
    for (int o = 16; o > 0; o >>= 1) v += __shfl_down_sync(0xffffffff, v, o);
    if ((t & 31) == 0) red[t >> 5] = v;
    __syncthreads();
    if (t == 0) out[g] = red[0] + red[1] + red[2] + red[3] + b3[0];
}

// ------------------------------------------------------------------ launch
extern "C" void kernel_launch(void* const* d_in, const int* in_sizes, int n_in,
                              void* d_out, int out_size) {
    const float* x         = (const float*)d_in[0];
    const float* edge_attr = (const float*)d_in[1];
    const float* charge    = (const float*)d_in[2];
    const int*   eidx      = (const int*)d_in[3];
    const int*   batch     = (const int*)d_in[4];
    const float* W_charge  = (const float*)d_in[5];
    const float* b_charge  = (const float*)d_in[6];
    const float* W_atom    = (const float*)d_in[7];
    const float* b_atom    = (const float*)d_in[8];
    const float* W_bond    = (const float*)d_in[9];
    const float* b_bond    = (const float*)d_in[10];
    const float* nu_W1     = (const float*)d_in[11];
    const float* nu_b1     = (const float*)d_in[12];
    const float* nu_W2     = (const float*)d_in[13];
    const float* nu_b2     = (const float*)d_in[14];
    const float* eu_W1     = (const float*)d_in[15];
    const float* eu_b1     = (const float*)d_in[16];
    const float* eu_W2     = (const float*)d_in[17];
    const float* eu_b2     = (const float*)d_in[18];
    const float* bn_g      = (const float*)d_in[19];
    const float* bn_b      = (const float*)d_in[20];
    const float* p_W1      = (const float*)d_in[21];
    const float* p_b1      = (const float*)d_in[22];
    const float* p_W2      = (const float*)d_in[23];
    const float* p_b2      = (const float*)d_in[24];
    const float* p_W3      = (const float*)d_in[25];
    const float* p_b3      = (const float*)d_in[26];
    float* out = (float*)d_out;

    const int PRE_SMEM  = (128 * 36 + 2 * 192 * 36) * 4;       // 73728
    const int EDGE_SMEM = (2 * 128 * 36 + 4 * 2 * 2304) * 4;   // 110592 (dyn only)
    cudaFuncSetAttribute(k_precompute, cudaFuncAttributeMaxDynamicSharedMemorySize, PRE_SMEM);
    cudaFuncSetAttribute(k_edge, cudaFuncAttributeMaxDynamicSharedMemorySize, EDGE_SMEM);

    k_charge<<<64, 256>>>(charge, W_charge, b_charge);
    k_cvt_all<<<22, 256>>>(eu_W1, eu_b1, nu_W1, nu_b1, eu_W2, nu_W2, W_bond);
    k_embed_nodes<<<(NN + 63) / 64, 256>>>(x, batch, W_atom, b_atom);
    k_embed_edges_mma<<<NT_EDGE, 256>>>(edge_attr, b_bond);

    for (int i = 0; i < LL; i++) {
        k_precompute<<<(NN + 127) / 128, 256, PRE_SMEM>>>(i);
        k_edge<<<296, 256, EDGE_SMEM>>>(eidx, i, eu_b2 + i * 64, nu_b2 + i * 64,
                                        i < LL - 1 ? 1 : 0);
        k_stats<<<256, 256>>>();
        k_finalize<<<1, 64>>>(bn_g + i * 64, bn_b + i * 64);
        k_update<<<(NN * DD) / 256, 256>>>(batch, i == LL - 1 ? 1 : 0);
    }

    k_predict<<<GG, 128>>>(p_W1, p_b1, p_W2, p_b2, p_W3, p_b3, out);
}

// round 10
// speedup vs baseline: 1.1048x; 1.1048x over previous
#include <cuda_runtime.h>
#include <cuda_bf16.h>
#include <math.h>

#define NN 50000
#define EE 500000
#define GG 256
#define DD 64
#define LL 3
#define NT_EDGE ((EE + 127) / 128)

// ------------------------------------------------------------------ globals
__device__ float    g_h[NN * DD];
__device__ unsigned g_ea[(size_t)EE * 32];      // bf16x2 words
__device__ float    g_Ar[NN * DD];
__device__ float    g_Ac[NN * DD];
__device__ float    g_Br[NN * DD];
__device__ float    g_hnew[NN * DD];
__device__ double   g_stats[2 * DD];
__device__ float    g_ab[2 * DD];
__device__ float    g_pool[GG * DD];
__device__ float    g_cnt[GG];
__device__ float    g_cf[GG * 16];

__device__ unsigned g_wbond[2][64 * 36];
__device__ unsigned g_wpre[LL][2][192 * 36];
__device__ unsigned g_wedge[LL][4][2][64 * 36];
__device__ unsigned g_watom[2][64 * 68];        // K=112 padded, LD=68 words
__device__ float    g_bpre[LL][192];

__device__ __forceinline__ float sp_f(float x) {
    return x > 15.f ? x : __logf(1.f + __expf(x));
}
__device__ __forceinline__ int clampi(int v, int hi) {
    return v < 0 ? 0 : (v >= hi ? hi - 1 : v);
}
__device__ __forceinline__ unsigned pack2(float x, float y) {
    __nv_bfloat162 h = __floats2bfloat162_rn(x, y);
    return *reinterpret_cast<unsigned*>(&h);
}
__device__ __forceinline__ void red2(float* a, float x, float y) {
    asm volatile("red.global.add.v2.f32 [%0], {%1,%2};" :: "l"(a), "f"(x), "f"(y) : "memory");
}
__device__ __forceinline__ void mma_bf16(float& c0, float& c1, float& c2, float& c3,
                                         unsigned a0, unsigned a1, unsigned a2, unsigned a3,
                                         unsigned b0, unsigned b1) {
    asm volatile("mma.sync.aligned.m16n8k16.row.col.f32.bf16.bf16.f32 "
                 "{%0,%1,%2,%3}, {%4,%5,%6,%7}, {%8,%9}, {%0,%1,%2,%3};\n"
                 : "+f"(c0), "+f"(c1), "+f"(c2), "+f"(c3)
                 : "r"(a0), "r"(a1), "r"(a2), "r"(a3), "r"(b0), "r"(b1));
}

template<int K0, int NT, int LD>
__device__ __forceinline__ void mma_tiles(const unsigned* sA, const unsigned* sWhi,
                                          const unsigned* sWlo, float acc[][NT][4],
                                          int wm, int wcol0, int gid, int tig) {
#pragma unroll
    for (int k0 = 0; k0 < K0; k0++) {
        unsigned a[2][4];
#pragma unroll
        for (int mt = 0; mt < 2; mt++) {
            const unsigned* base = &sA[(wm * 32 + mt * 16 + gid) * LD + k0 * 8 + tig];
            a[mt][0] = base[0];
            a[mt][1] = base[8 * LD];
            a[mt][2] = base[4];
            a[mt][3] = base[8 * LD + 4];
        }
#pragma unroll
        for (int nt = 0; nt < NT; nt++) {
            int off = (wcol0 + nt * 8 + gid) * LD + k0 * 8 + tig;
            unsigned bh0 = sWhi[off], bh1 = sWhi[off + 4];
            unsigned bl0 = sWlo[off], bl1 = sWlo[off + 4];
#pragma unroll
            for (int mt = 0; mt < 2; mt++) {
                mma_bf16(acc[mt][nt][0], acc[mt][nt][1], acc[mt][nt][2], acc[mt][nt][3],
                         a[mt][0], a[mt][1], a[mt][2], a[mt][3], bh0, bh1);
                mma_bf16(acc[mt][nt][0], acc[mt][nt][1], acc[mt][nt][2], acc[mt][nt][3],
                         a[mt][0], a[mt][1], a[mt][2], a[mt][3], bl0, bl1);
            }
        }
    }
}

// ------------------------------------------------------------------ one-time weight conversion
__global__ void k_cvt_all(const float* eu_W1, const float* eu_b1,
                          const float* nu_W1, const float* nu_b1,
                          const float* eu_W2, const float* nu_W2,
                          const float* W_bond, const float* W_atom) {
    int b = blockIdx.x, tid = threadIdx.x;
    if (b == 22) {   // W_atom: [108 x 64] -> hi/lo, LD=136 halves
        __nv_bfloat16* hhi = reinterpret_cast<__nv_bfloat16*>(g_watom[0]);
        __nv_bfloat16* hlo = reinterpret_cast<__nv_bfloat16*>(g_watom[1]);
        for (int idx = tid; idx < 112 * 64; idx += 256) {
            int k = idx >> 6, n = idx & 63;
            float w = (k < 108) ? W_atom[k * 64 + n] : 0.f;
            __nv_bfloat16 hi = __float2bfloat16(w);
            float lo = w - __bfloat162float(hi);
            hhi[(size_t)n * 136 + k] = hi;
            hlo[(size_t)n * 136 + k] = __float2bfloat16(lo);
        }
        return;
    }
    const float* src; unsigned *dhi, *dlo; int ncoff = 0, validK = 64;
    if (b == 0) {
        src = W_bond; validK = 41;
        dhi = g_wbond[0]; dlo = g_wbond[1];
        for (int idx = tid; idx < LL * 192; idx += 256) {
            int i = idx / 192, n = idx % 192;
            float v = 0.f;
            if (n < 64)        v = eu_b1[i * 64 + n];
            else if (n >= 128) v = nu_b1[i * 64 + (n - 128)];
            g_bpre[i][n] = v;
        }
    } else {
        int i = (b - 1) / 7, j = (b - 1) % 7;
        const float* euW1 = eu_W1 + (size_t)i * 12288;
        const float* nuW1 = nu_W1 + (size_t)i * 8192;
        switch (j) {
            case 0: src = euW1;            dhi = g_wpre[i][0]; dlo = g_wpre[i][1]; ncoff = 0;   break;
            case 1: src = euW1 + 4096;     dhi = g_wpre[i][0]; dlo = g_wpre[i][1]; ncoff = 64;  break;
            case 2: src = nuW1;            dhi = g_wpre[i][0]; dlo = g_wpre[i][1]; ncoff = 128; break;
            case 3: src = euW1 + 8192;     dhi = g_wedge[i][0][0]; dlo = g_wedge[i][0][1]; break;
            case 4: src = eu_W2 + (size_t)i * 4096; dhi = g_wedge[i][1][0]; dlo = g_wedge[i][1][1]; break;
            case 5: src = nuW1 + 4096;     dhi = g_wedge[i][2][0]; dlo = g_wedge[i][2][1]; break;
            default: src = nu_W2 + (size_t)i * 4096; dhi = g_wedge[i][3][0]; dlo = g_wedge[i][3][1]; break;
        }
    }
    __nv_bfloat16* hhi = reinterpret_cast<__nv_bfloat16*>(dhi);
    __nv_bfloat16* hlo = reinterpret_cast<__nv_bfloat16*>(dlo);
    for (int idx = tid; idx < 4096; idx += 256) {
        int k = idx >> 6, n = idx & 63;
        float w = (k < validK) ? src[k * 64 + n] : 0.f;
        __nv_bfloat16 hi = __float2bfloat16(w);
        float lo = w - __bfloat162float(hi);
        hhi[(size_t)(n + ncoff) * 72 + k] = hi;
        hlo[(size_t)(n + ncoff) * 72 + k] = __float2bfloat16(lo);
    }
}

// ------------------------------------------------------------------ small kernels
__global__ void k_charge(const float* charge, const float* Wc, const float* bc) {
    int i = blockIdx.x * 256 + threadIdx.x;
    if (i < GG * 16) g_cf[i] = charge[i >> 4] * Wc[i & 15] + bc[i & 15];
    if (i < GG * DD) g_pool[i] = 0.f;
    if (i < GG) g_cnt[i] = 0.f;
}

// ------------------------------------------------------------------ node embedding via MMA (K=112)
__global__ __launch_bounds__(256) void k_embed_nodes_mma(
    const float* x, const int* batch, const float* b) {
    extern __shared__ unsigned dyn[];
    unsigned* sA = dyn;                  // 128*68
    unsigned* sW = dyn + 128 * 68;       // 2 * 64*68 (hi, lo)
    int tid = threadIdx.x, n0 = blockIdx.x * 128;
    int warp = tid >> 5, lane = tid & 31;
    int wm = warp >> 1, wn = warp & 1;
    int gid = lane >> 2, tig = lane & 3;

    {
        const uint4* src = reinterpret_cast<const uint4*>(g_watom[0]);
        uint4* dst = reinterpret_cast<uint4*>(sW);
        for (int idx = tid; idx < 2 * 64 * 68 / 4; idx += 256) dst[idx] = src[idx];
    }
    for (int idx = tid; idx < 128 * 56; idx += 256) {
        int nr = idx / 56, kw = idx - nr * 56;
        int n = n0 + nr; if (n >= NN) n = NN - 1;
        int k = kw * 2;
        float v0, v1;
        int bb = clampi(batch[n], GG);
        v0 = (k < 92)      ? x[(size_t)n * 92 + k]
           : (k < 108)     ? g_cf[bb * 16 + (k - 92)] : 0.f;
        int k1 = k + 1;
        v1 = (k1 < 92)     ? x[(size_t)n * 92 + k1]
           : (k1 < 108)    ? g_cf[bb * 16 + (k1 - 92)] : 0.f;
        sA[nr * 68 + kw] = pack2(v0, v1);
    }
    __syncthreads();

    float acc[2][4][4];
#pragma unroll
    for (int mt = 0; mt < 2; mt++)
#pragma unroll
        for (int nt = 0; nt < 4; nt++) {
            float2 bv = *reinterpret_cast<const float2*>(&b[wn * 32 + nt * 8 + tig * 2]);
            acc[mt][nt][0] = bv.x; acc[mt][nt][1] = bv.y;
            acc[mt][nt][2] = bv.x; acc[mt][nt][3] = bv.y;
        }
    mma_tiles<7, 4, 68>(sA, sW, sW + 64 * 68, acc, wm, wn * 32, gid, tig);
#pragma unroll
    for (int mt = 0; mt < 2; mt++)
#pragma unroll
        for (int nt = 0; nt < 4; nt++) {
            int row = wm * 32 + mt * 16 + gid;
            int col = wn * 32 + nt * 8 + tig * 2;
            int n = n0 + row;
            if (n < NN)
                *reinterpret_cast<float2*>(&g_h[(size_t)n * 64 + col]) =
                    make_float2(acc[mt][nt][0], acc[mt][nt][1]);
            if (n + 8 < NN)
                *reinterpret_cast<float2*>(&g_h[(size_t)(n + 8) * 64 + col]) =
                    make_float2(acc[mt][nt][2], acc[mt][nt][3]);
        }
}

// ------------------------------------------------------------------ edge embedding (non-persistent)
__global__ __launch_bounds__(256) void k_embed_edges_mma(const float* ea, const float* b) {
    __shared__ unsigned sA[128 * 36];
    __shared__ unsigned sW[2 * 64 * 36];
    int tid = threadIdx.x, e0 = blockIdx.x * 128;
    int warp = tid >> 5, lane = tid & 31;
    int wm = warp >> 1, wn = warp & 1;
    int gid = lane >> 2, tig = lane & 3;

    {
        const uint4* src = reinterpret_cast<const uint4*>(g_wbond[0]);
        uint4* dst = reinterpret_cast<uint4*>(sW);
        for (int idx = tid; idx < 2 * 64 * 36 / 4; idx += 256) dst[idx] = src[idx];
    }
    for (int idx = tid; idx < 128 * 24; idx += 256) {
        int er = idx / 24, kw = idx - er * 24;
        int k = kw * 2;
        int e = e0 + er; if (e >= EE) e = EE - 1;
        float v0 = (k < 41)     ? ea[(size_t)e * 41 + k]     : 0.f;
        float v1 = (k + 1 < 41) ? ea[(size_t)e * 41 + k + 1] : 0.f;
        sA[er * 36 + kw] = pack2(v0, v1);
    }
    __syncthreads();

    float acc[2][4][4];
#pragma unroll
    for (int mt = 0; mt < 2; mt++)
#pragma unroll
        for (int nt = 0; nt < 4; nt++) {
            float2 bv = *reinterpret_cast<const float2*>(&b[wn * 32 + nt * 8 + tig * 2]);
            acc[mt][nt][0] = bv.x; acc[mt][nt][1] = bv.y;
            acc[mt][nt][2] = bv.x; acc[mt][nt][3] = bv.y;
        }
    mma_tiles<3, 4, 36>(sA, sW, sW + 64 * 36, acc, wm, wn * 32, gid, tig);
#pragma unroll
    for (int mt = 0; mt < 2; mt++)
#pragma unroll
        for (int nt = 0; nt < 4; nt++) {
            int row = wm * 32 + mt * 16 + gid;
            int cw = wn * 16 + nt * 4 + tig;
            int e = e0 + row;
            if (e < EE)     g_ea[(size_t)e * 32 + cw]       = pack2(acc[mt][nt][0], acc[mt][nt][1]);
            if (e + 8 < EE) g_ea[(size_t)(e + 8) * 32 + cw] = pack2(acc[mt][nt][2], acc[mt][nt][3]);
        }
}

// ------------------------------------------------------------------ fused precompute (Ar|Ac|Br)
__global__ __launch_bounds__(256) void k_precompute(int layer) {
    extern __shared__ unsigned dyn[];
    unsigned* sA = dyn;
    unsigned* sW = dyn + 128 * 36;
    int tid = threadIdx.x, n0 = blockIdx.x * 128;
    int warp = tid >> 5, lane = tid & 31;
    int wm = warp >> 1, wn = warp & 1;
    int gid = lane >> 2, tig = lane & 3;
    if (blockIdx.x == 0 && tid < 128) g_stats[tid] = 0.0;

    {
        const uint4* src = reinterpret_cast<const uint4*>(g_wpre[layer][0]);
        uint4* dst = reinterpret_cast<uint4*>(sW);
        for (int idx = tid; idx < 2 * 192 * 36 / 4; idx += 256) dst[idx] = src[idx];
    }
    for (int idx = tid; idx < 128 * 32; idx += 256) {
        int nr = idx >> 5, cw = idx & 31;
        int n = n0 + nr;
        if (n < NN) {
            float2 v = *reinterpret_cast<const float2*>(&g_h[(size_t)n * 64 + cw * 2]);
            sA[nr * 36 + cw] = pack2(v.x, v.y);
            *reinterpret_cast<float2*>(&g_hnew[(size_t)n * 64 + cw * 2]) = make_float2(0.f, 0.f);
        } else sA[nr * 36 + cw] = 0u;
    }
    __syncthreads();

    float acc[2][12][4];
#pragma unroll
    for (int mt = 0; mt < 2; mt++)
#pragma unroll
        for (int nt = 0; nt < 12; nt++) {
            int nc = wn * 96 + nt * 8 + tig * 2;
            float2 bv = *reinterpret_cast<const float2*>(&g_bpre[layer][nc]);
            acc[mt][nt][0] = bv.x; acc[mt][nt][1] = bv.y;
            acc[mt][nt][2] = bv.x; acc[mt][nt][3] = bv.y;
        }
    mma_tiles<4, 12, 36>(sA, sW, sW + 192 * 36, acc, wm, wn * 96, gid, tig);
#pragma unroll
    for (int mt = 0; mt < 2; mt++)
#pragma unroll
        for (int nt = 0; nt < 12; nt++) {
            int nc = wn * 96 + nt * 8 + tig * 2;
            float* O = nc < 64 ? g_Ar : (nc < 128 ? g_Ac : g_Br);
            int col = nc & 63;
            int row = wm * 32 + mt * 16 + gid;
            int n = n0 + row;
            if (n < NN)
                *reinterpret_cast<float2*>(&O[(size_t)n * 64 + col]) =
                    make_float2(acc[mt][nt][0], acc[mt][nt][1]);
            if (n + 8 < NN)
                *reinterpret_cast<float2*>(&O[(size_t)(n + 8) * 64 + col]) =
                    make_float2(acc[mt][nt][2], acc[mt][nt][3]);
        }
}

// ------------------------------------------------------------------ fused edge pipeline (R7 config)
__global__ __launch_bounds__(256, 2) void k_edge(const int* eidx, int layer,
                                                 const float* b2, const float* b4,
                                                 int store_ea) {
    extern __shared__ unsigned dyn[];
    unsigned* sA = dyn;                    // 128*36
    unsigned* sW = dyn + 128 * 36;         // 4 stages * (hi 2304 + lo 2304)
    __shared__ float sB2[64], sB4[64];
    __shared__ int sRow[128], sCol[128];

    int tid = threadIdx.x;
    int warp = tid >> 5, lane = tid & 31;
    int wm = warp >> 1, wn = warp & 1;
    int gid = lane >> 2, tig = lane & 3;

    if (tid < 64) { sB2[tid] = b2[tid]; sB4[tid] = b4[tid]; }
    {
        const uint4* src = reinterpret_cast<const uint4*>(&g_wedge[layer][0][0][0]);
        uint4* dst = reinterpret_cast<uint4*>(sW);
        for (int idx = tid; idx < 4 * 2 * 2304 / 4; idx += 256) dst[idx] = src[idx];
    }
    const unsigned* W1h = sW;
    const unsigned* W2h = sW + 4608;
    const unsigned* W3h = sW + 9216;
    const unsigned* W4h = sW + 13824;

    for (int t = blockIdx.x; t < NT_EDGE; t += gridDim.x) {
        int e0 = t * 128;
        __syncthreads();                       // prior tile fully consumed
        if (tid < 128) {
            int e = e0 + tid; if (e >= EE) e = EE - 1;
            sRow[tid] = clampi(eidx[e], NN);
            sCol[tid] = clampi(eidx[EE + e], NN);
        }
        for (int idx = tid; idx < 128 * 32; idx += 256) {
            int er = idx >> 5, cw = idx & 31;
            int e = e0 + er; if (e >= EE) e = EE - 1;
            sA[er * 36 + cw] = g_ea[(size_t)e * 32 + cw];
        }
        __syncthreads();

        float acc[2][4][4];

        // ---- stage 1: t = sp(sA @ W1c + Ar[row] + Ac[col])
#pragma unroll
        for (int mt = 0; mt < 2; mt++)
#pragma unroll
            for (int nt = 0; nt < 4; nt++) {
                int row = wm * 32 + mt * 16 + gid;
                int col = wn * 32 + nt * 8 + tig * 2;
                int r0 = sRow[row], c0 = sCol[row];
                int r1 = sRow[row + 8], c1 = sCol[row + 8];
                float2 a0 = *reinterpret_cast<const float2*>(&g_Ar[(size_t)r0 * 64 + col]);
                float2 q0 = *reinterpret_cast<const float2*>(&g_Ac[(size_t)c0 * 64 + col]);
                float2 a1 = *reinterpret_cast<const float2*>(&g_Ar[(size_t)r1 * 64 + col]);
                float2 q1 = *reinterpret_cast<const float2*>(&g_Ac[(size_t)c1 * 64 + col]);
                acc[mt][nt][0] = a0.x + q0.x; acc[mt][nt][1] = a0.y + q0.y;
                acc[mt][nt][2] = a1.x + q1.x; acc[mt][nt][3] = a1.y + q1.y;
            }
        mma_tiles<4, 4, 36>(sA, W1h, W1h + 2304, acc, wm, wn * 32, gid, tig);
        __syncthreads();
#pragma unroll
        for (int mt = 0; mt < 2; mt++)
#pragma unroll
            for (int nt = 0; nt < 4; nt++) {
                int row = wm * 32 + mt * 16 + gid;
                int cw = wn * 16 + nt * 4 + tig;
                sA[row * 36 + cw]       = pack2(sp_f(acc[mt][nt][0]), sp_f(acc[mt][nt][1]));
                sA[(row + 8) * 36 + cw] = pack2(sp_f(acc[mt][nt][2]), sp_f(acc[mt][nt][3]));
            }
        __syncthreads();

        // ---- stage 2: ea_new = sA @ W2 + b2
#pragma unroll
        for (int mt = 0; mt < 2; mt++)
#pragma unroll
            for (int nt = 0; nt < 4; nt++) {
                int col = wn * 32 + nt * 8 + tig * 2;
                float2 bv = *reinterpret_cast<const float2*>(&sB2[col]);
                acc[mt][nt][0] = bv.x; acc[mt][nt][1] = bv.y;
                acc[mt][nt][2] = bv.x; acc[mt][nt][3] = bv.y;
            }
        mma_tiles<4, 4, 36>(sA, W2h, W2h + 2304, acc, wm, wn * 32, gid, tig);
        __syncthreads();
#pragma unroll
        for (int mt = 0; mt < 2; mt++)
#pragma unroll
            for (int nt = 0; nt < 4; nt++) {
                int row = wm * 32 + mt * 16 + gid;
                int cw = wn * 16 + nt * 4 + tig;
                unsigned p0 = pack2(acc[mt][nt][0], acc[mt][nt][1]);
                unsigned p1 = pack2(acc[mt][nt][2], acc[mt][nt][3]);
                sA[row * 36 + cw]       = p0;
                sA[(row + 8) * 36 + cw] = p1;
                if (store_ea) {
                    int e = e0 + row;
                    if (e < EE)     g_ea[(size_t)e * 32 + cw]       = p0;
                    if (e + 8 < EE) g_ea[(size_t)(e + 8) * 32 + cw] = p1;
                }
            }
        __syncthreads();

        // ---- stage 3: u = sp(sA @ W3 + Br[row])
#pragma unroll
        for (int mt = 0; mt < 2; mt++)
#pragma unroll
            for (int nt = 0; nt < 4; nt++) {
                int row = wm * 32 + mt * 16 + gid;
                int col = wn * 32 + nt * 8 + tig * 2;
                float2 v0 = *reinterpret_cast<const float2*>(&g_Br[(size_t)sRow[row] * 64 + col]);
                float2 v1 = *reinterpret_cast<const float2*>(&g_Br[(size_t)sRow[row + 8] * 64 + col]);
                acc[mt][nt][0] = v0.x; acc[mt][nt][1] = v0.y;
                acc[mt][nt][2] = v1.x; acc[mt][nt][3] = v1.y;
            }
        mma_tiles<4, 4, 36>(sA, W3h, W3h + 2304, acc, wm, wn * 32, gid, tig);
        __syncthreads();
#pragma unroll
        for (int mt = 0; mt < 2; mt++)
#pragma unroll
            for (int nt = 0; nt < 4; nt++) {
                int row = wm * 32 + mt * 16 + gid;
                int cw = wn * 16 + nt * 4 + tig;
                sA[row * 36 + cw]       = pack2(sp_f(acc[mt][nt][0]), sp_f(acc[mt][nt][1]));
                sA[(row + 8) * 36 + cw] = pack2(sp_f(acc[mt][nt][2]), sp_f(acc[mt][nt][3]));
            }
        __syncthreads();

        // ---- stage 4: msg = sA @ W4 + b4 -> vector red scatter
#pragma unroll
        for (int mt = 0; mt < 2; mt++)
#pragma unroll
            for (int nt = 0; nt < 4; nt++) {
                int col = wn * 32 + nt * 8 + tig * 2;
                float2 bv = *reinterpret_cast<const float2*>(&sB4[col]);
                acc[mt][nt][0] = bv.x; acc[mt][nt][1] = bv.y;
                acc[mt][nt][2] = bv.x; acc[mt][nt][3] = bv.y;
            }
        mma_tiles<4, 4, 36>(sA, W4h, W4h + 2304, acc, wm, wn * 32, gid, tig);
#pragma unroll
        for (int mt = 0; mt < 2; mt++)
#pragma unroll
            for (int nt = 0; nt < 4; nt++) {
                int row = wm * 32 + mt * 16 + gid;
                int col = wn * 32 + nt * 8 + tig * 2;
                int e = e0 + row;
                if (e < EE)
                    red2(&g_hnew[(size_t)sCol[row] * 64 + col], acc[mt][nt][0], acc[mt][nt][1]);
                if (e + 8 < EE)
                    red2(&g_hnew[(size_t)sCol[row + 8] * 64 + col], acc[mt][nt][2], acc[mt][nt][3]);
            }
    }
}

// ------------------------------------------------------------------ tail kernels
__global__ void k_stats() {
    int c = threadIdx.x & 63, rr = threadIdx.x >> 6;
    double s = 0.0, s2 = 0.0;
    for (int n = blockIdx.x * 4 + rr; n < NN; n += gridDim.x * 4) {
        float v = g_hnew[n * 64 + c];
        s += v; s2 += (double)v * v;
    }
    __shared__ double sh[8][64];
    sh[rr][c] = s; sh[4 + rr][c] = s2;
    __syncthreads();
    if (rr == 0) {
        atomicAdd(&g_stats[c],      sh[0][c] + sh[1][c] + sh[2][c] + sh[3][c]);
        atomicAdd(&g_stats[64 + c], sh[4][c] + sh[5][c] + sh[6][c] + sh[7][c]);
    }
}

__global__ void k_finalize(const float* gamma, const float* beta) {
    int j = threadIdx.x;
    double mu = g_stats[j] / (double)NN;
    double var = g_stats[64 + j] / (double)NN - mu * mu;
    float a = rsqrtf((float)var + 1e-5f) * gamma[j];
    g_ab[j] = a;
    g_ab[64 + j] = beta[j] - (float)mu * a;
}

// BN-apply + softplus + residual; on last layer also fused global mean pool
__global__ void k_update(const int* batch, int do_pool) {
    int idx = blockIdx.x * 256 + threadIdx.x;
    int j = idx & 63;
    float v = g_hnew[idx] * g_ab[j] + g_ab[64 + j];
    float h = sp_f(v) + g_h[idx];
    g_h[idx] = h;
    if (do_pool) {
        int b = clampi(batch[idx >> 6], GG);
        atomicAdd(&g_pool[b * 64 + j], h);
        if (j == 0) atomicAdd(&g_cnt[b], 1.f);
    }
}

__global__ void k_predict(const float* W1, const float* b1,
                          const float* W2, const float* b2,
                          const float* W3, const float* b3, float* out) {
    __shared__ float gr[64], z1[128], z2[128];
    __shared__ float red[4];
    int g = blockIdx.x, t = threadIdx.x;
    if (t < 64) gr[t] = g_pool[g * 64 + t] / fmaxf(g_cnt[g], 1.f);
    __syncthreads();
    float acc = b1[t];
    for (int k = 0; k < 64; k++) acc = fmaf(gr[k], W1[k * 128 + t], acc);
    z1[t] = sp_f(acc);
    __syncthreads();
    acc = b2[t];
    for (int k = 0; k < 128; k++) acc = fmaf(z1[k], W2[k * 128 + t], acc);
    z2[t] = sp_f(acc);
    __syncthreads();
    float v = z2[t] * W3[t];
    for (int o = 16; o > 0; o >>= 1) v += __shfl_down_sync(0xffffffff, v, o);
    if ((t & 31) == 0) red[t >> 5] = v;
    __syncthreads();
    if (t == 0) out[g] = red[0] + red[1] + red[2] + red[3] + b3[0];
}

// ------------------------------------------------------------------ launch
extern "C" void kernel_launch(void* const* d_in, const int* in_sizes, int n_in,
                              void* d_out, int out_size) {
    const float* x         = (const float*)d_in[0];
    const float* edge_attr = (const float*)d_in[1];
    const float* charge    = (const float*)d_in[2];
    const int*   eidx      = (const int*)d_in[3];
    const int*   batch     = (const int*)d_in[4];
    const float* W_charge  = (const float*)d_in[5];
    const float* b_charge  = (const float*)d_in[6];
    const float* W_atom    = (const float*)d_in[7];
    const float* b_atom    = (const float*)d_in[8];
    const float* W_bond    = (const float*)d_in[9];
    const float* b_bond    = (const float*)d_in[10];
    const float* nu_W1     = (const float*)d_in[11];
    const float* nu_b1     = (const float*)d_in[12];
    const float* nu_W2     = (const float*)d_in[13];
    const float* nu_b2     = (const float*)d_in[14];
    const float* eu_W1     = (const float*)d_in[15];
    const float* eu_b1     = (const float*)d_in[16];
    const float* eu_W2     = (const float*)d_in[17];
    const float* eu_b2     = (const float*)d_in[18];
    const float* bn_g      = (const float*)d_in[19];
    const float* bn_b      = (const float*)d_in[20];
    const float* p_W1      = (const float*)d_in[21];
    const float* p_b1      = (const float*)d_in[22];
    const float* p_W2      = (const float*)d_in[23];
    const float* p_b2      = (const float*)d_in[24];
    const float* p_W3      = (const float*)d_in[25];
    const float* p_b3      = (const float*)d_in[26];
    float* out = (float*)d_out;

    const int PRE_SMEM  = (128 * 36 + 2 * 192 * 36) * 4;   // 73728
    const int EDGE_SMEM = (128 * 36 + 4 * 2 * 2304) * 4;   // 92160
    const int EN_SMEM   = (128 * 68 + 2 * 64 * 68) * 4;    // 69632
    cudaFuncSetAttribute(k_precompute, cudaFuncAttributeMaxDynamicSharedMemorySize, PRE_SMEM);
    cudaFuncSetAttribute(k_edge, cudaFuncAttributeMaxDynamicSharedMemorySize, EDGE_SMEM);
    cudaFuncSetAttribute(k_embed_nodes_mma, cudaFuncAttributeMaxDynamicSharedMemorySize, EN_SMEM);

    k_charge<<<64, 256>>>(charge, W_charge, b_charge);
    k_cvt_all<<<23, 256>>>(eu_W1, eu_b1, nu_W1, nu_b1, eu_W2, nu_W2, W_bond, W_atom);
    k_embed_nodes_mma<<<(NN + 127) / 128, 256, EN_SMEM>>>(x, batch, b_atom);
    k_embed_edges_mma<<<NT_EDGE, 256>>>(edge_attr, b_bond);

    for (int i = 0; i < LL; i++) {
        k_precompute<<<(NN + 127) / 128, 256, PRE_SMEM>>>(i);
        k_edge<<<296, 256, EDGE_SMEM>>>(eidx, i, eu_b2 + i * 64, nu_b2 + i * 64,
                                        i < LL - 1 ? 1 : 0);
        k_stats<<<256, 256>>>();
        k_finalize<<<1, 64>>>(bn_g + i * 64, bn_b + i * 64);
        k_update<<<(NN * DD) / 256, 256>>>(batch, i == LL - 1 ? 1 : 0);
    }

    k_predict<<<GG, 128>>>(p_W1, p_b1, p_W2, p_b2, p_W3, p_b3, out);
}

// round 11
// speedup vs baseline: 1.1859x; 1.0735x over previous
#include <cuda_runtime.h>
#include <cuda_bf16.h>
#include <math.h>

#define NN 50000
#define EE 500000
#define GG 256
#define DD 64
#define LL 3
#define NT_EDGE ((EE + 127) / 128)

// ------------------------------------------------------------------ globals
__device__ float    g_h[NN * DD];
__device__ unsigned g_ea[(size_t)EE * 32];      // bf16x2 words
__device__ unsigned g_Arh[NN * 32];             // bf16x2 gather tables
__device__ unsigned g_Ach[NN * 32];
__device__ unsigned g_Brh[NN * 32];
__device__ float    g_hnew[NN * DD];
__device__ double   g_stats[2 * DD];
__device__ float    g_ab[2 * DD];
__device__ float    g_pool[GG * DD];
__device__ float    g_cnt[GG];
__device__ float    g_cf[GG * 16];

__device__ unsigned g_wbond[2][64 * 36];
__device__ unsigned g_wpre[LL][2][192 * 36];
__device__ unsigned g_wedge[LL][4][2][64 * 36];
__device__ unsigned g_watom[2][64 * 68];        // K=112 padded, LD=68 words
__device__ float    g_bpre[LL][192];

__device__ __forceinline__ float sp_f(float x) {
    return x > 15.f ? x : __logf(1.f + __expf(x));
}
__device__ __forceinline__ int clampi(int v, int hi) {
    return v < 0 ? 0 : (v >= hi ? hi - 1 : v);
}
__device__ __forceinline__ unsigned pack2(float x, float y) {
    __nv_bfloat162 h = __floats2bfloat162_rn(x, y);
    return *reinterpret_cast<unsigned*>(&h);
}
__device__ __forceinline__ float2 up2(unsigned u) {
    __nv_bfloat162 h = *reinterpret_cast<__nv_bfloat162*>(&u);
    return __bfloat1622float2(h);
}
__device__ __forceinline__ void red2(float* a, float x, float y) {
    asm volatile("red.global.add.v2.f32 [%0], {%1,%2};" :: "l"(a), "f"(x), "f"(y) : "memory");
}
__device__ __forceinline__ void mma_bf16(float& c0, float& c1, float& c2, float& c3,
                                         unsigned a0, unsigned a1, unsigned a2, unsigned a3,
                                         unsigned b0, unsigned b1) {
    asm volatile("mma.sync.aligned.m16n8k16.row.col.f32.bf16.bf16.f32 "
                 "{%0,%1,%2,%3}, {%4,%5,%6,%7}, {%8,%9}, {%0,%1,%2,%3};\n"
                 : "+f"(c0), "+f"(c1), "+f"(c2), "+f"(c3)
                 : "r"(a0), "r"(a1), "r"(a2), "r"(a3), "r"(b0), "r"(b1));
}

template<int K0, int NT, int LD>
__device__ __forceinline__ void mma_tiles(const unsigned* sA, const unsigned* sWhi,
                                          const unsigned* sWlo, float acc[][NT][4],
                                          int wm, int wcol0, int gid, int tig) {
#pragma unroll
    for (int k0 = 0; k0 < K0; k0++) {
        unsigned a[2][4];
#pragma unroll
        for (int mt = 0; mt < 2; mt++) {
            const unsigned* base = &sA[(wm * 32 + mt * 16 + gid) * LD + k0 * 8 + tig];
            a[mt][0] = base[0];
            a[mt][1] = base[8 * LD];
            a[mt][2] = base[4];
            a[mt][3] = base[8 * LD + 4];
        }
#pragma unroll
        for (int nt = 0; nt < NT; nt++) {
            int off = (wcol0 + nt * 8 + gid) * LD + k0 * 8 + tig;
            unsigned bh0 = sWhi[off], bh1 = sWhi[off + 4];
            unsigned bl0 = sWlo[off], bl1 = sWlo[off + 4];
#pragma unroll
            for (int mt = 0; mt < 2; mt++) {
                mma_bf16(acc[mt][nt][0], acc[mt][nt][1], acc[mt][nt][2], acc[mt][nt][3],
                         a[mt][0], a[mt][1], a[mt][2], a[mt][3], bh0, bh1);
                mma_bf16(acc[mt][nt][0], acc[mt][nt][1], acc[mt][nt][2], acc[mt][nt][3],
                         a[mt][0], a[mt][1], a[mt][2], a[mt][3], bl0, bl1);
            }
        }
    }
}

// ------------------------------------------------------------------ one-time weight conversion
__global__ void k_cvt_all(const float* eu_W1, const float* eu_b1,
                          const float* nu_W1, const float* nu_b1,
                          const float* eu_W2, const float* nu_W2,
                          const float* W_bond, const float* W_atom) {
    int b = blockIdx.x, tid = threadIdx.x;
    if (b == 22) {   // W_atom: [108 x 64] -> hi/lo, LD=136 halves
        __nv_bfloat16* hhi = reinterpret_cast<__nv_bfloat16*>(g_watom[0]);
        __nv_bfloat16* hlo = reinterpret_cast<__nv_bfloat16*>(g_watom[1]);
        for (int idx = tid; idx < 112 * 64; idx += 256) {
            int k = idx >> 6, n = idx & 63;
            float w = (k < 108) ? W_atom[k * 64 + n] : 0.f;
            __nv_bfloat16 hi = __float2bfloat16(w);
            float lo = w - __bfloat162float(hi);
            hhi[(size_t)n * 136 + k] = hi;
            hlo[(size_t)n * 136 + k] = __float2bfloat16(lo);
        }
        return;
    }
    const float* src; unsigned *dhi, *dlo; int ncoff = 0, validK = 64;
    if (b == 0) {
        src = W_bond; validK = 41;
        dhi = g_wbond[0]; dlo = g_wbond[1];
        for (int idx = tid; idx < LL * 192; idx += 256) {
            int i = idx / 192, n = idx % 192;
            float v = 0.f;
            if (n < 64)        v = eu_b1[i * 64 + n];
            else if (n >= 128) v = nu_b1[i * 64 + (n - 128)];
            g_bpre[i][n] = v;
        }
    } else {
        int i = (b - 1) / 7, j = (b - 1) % 7;
        const float* euW1 = eu_W1 + (size_t)i * 12288;
        const float* nuW1 = nu_W1 + (size_t)i * 8192;
        switch (j) {
            case 0: src = euW1;            dhi = g_wpre[i][0]; dlo = g_wpre[i][1]; ncoff = 0;   break;
            case 1: src = euW1 + 4096;     dhi = g_wpre[i][0]; dlo = g_wpre[i][1]; ncoff = 64;  break;
            case 2: src = nuW1;            dhi = g_wpre[i][0]; dlo = g_wpre[i][1]; ncoff = 128; break;
            case 3: src = euW1 + 8192;     dhi = g_wedge[i][0][0]; dlo = g_wedge[i][0][1]; break;
            case 4: src = eu_W2 + (size_t)i * 4096; dhi = g_wedge[i][1][0]; dlo = g_wedge[i][1][1]; break;
            case 5: src = nuW1 + 4096;     dhi = g_wedge[i][2][0]; dlo = g_wedge[i][2][1]; break;
            default: src = nu_W2 + (size_t)i * 4096; dhi = g_wedge[i][3][0]; dlo = g_wedge[i][3][1]; break;
        }
    }
    __nv_bfloat16* hhi = reinterpret_cast<__nv_bfloat16*>(dhi);
    __nv_bfloat16* hlo = reinterpret_cast<__nv_bfloat16*>(dlo);
    for (int idx = tid; idx < 4096; idx += 256) {
        int k = idx >> 6, n = idx & 63;
        float w = (k < validK) ? src[k * 64 + n] : 0.f;
        __nv_bfloat16 hi = __float2bfloat16(w);
        float lo = w - __bfloat162float(hi);
        hhi[(size_t)(n + ncoff) * 72 + k] = hi;
        hlo[(size_t)(n + ncoff) * 72 + k] = __float2bfloat16(lo);
    }
}

// ------------------------------------------------------------------ small kernels
__global__ void k_charge(const float* charge, const float* Wc, const float* bc) {
    int i = blockIdx.x * 256 + threadIdx.x;
    if (i < GG * 16) g_cf[i] = charge[i >> 4] * Wc[i & 15] + bc[i & 15];
    if (i < GG * DD) g_pool[i] = 0.f;
    if (i < GG) g_cnt[i] = 0.f;
}

// ------------------------------------------------------------------ node embedding via MMA (K=112)
__global__ __launch_bounds__(256) void k_embed_nodes_mma(
    const float* x, const int* batch, const float* b) {
    extern __shared__ unsigned dyn[];
    unsigned* sA = dyn;                  // 128*68
    unsigned* sW = dyn + 128 * 68;       // 2 * 64*68 (hi, lo)
    int tid = threadIdx.x, n0 = blockIdx.x * 128;
    int warp = tid >> 5, lane = tid & 31;
    int wm = warp >> 1, wn = warp & 1;
    int gid = lane >> 2, tig = lane & 3;

    {
        const uint4* src = reinterpret_cast<const uint4*>(g_watom[0]);
        uint4* dst = reinterpret_cast<uint4*>(sW);
        for (int idx = tid; idx < 2 * 64 * 68 / 4; idx += 256) dst[idx] = src[idx];
    }
    for (int idx = tid; idx < 128 * 56; idx += 256) {
        int nr = idx / 56, kw = idx - nr * 56;
        int n = n0 + nr; if (n >= NN) n = NN - 1;
        int k = kw * 2;
        float v0, v1;
        int bb = clampi(batch[n], GG);
        v0 = (k < 92)      ? x[(size_t)n * 92 + k]
           : (k < 108)     ? g_cf[bb * 16 + (k - 92)] : 0.f;
        int k1 = k + 1;
        v1 = (k1 < 92)     ? x[(size_t)n * 92 + k1]
           : (k1 < 108)    ? g_cf[bb * 16 + (k1 - 92)] : 0.f;
        sA[nr * 68 + kw] = pack2(v0, v1);
    }
    __syncthreads();

    float acc[2][4][4];
#pragma unroll
    for (int mt = 0; mt < 2; mt++)
#pragma unroll
        for (int nt = 0; nt < 4; nt++) {
            float2 bv = *reinterpret_cast<const float2*>(&b[wn * 32 + nt * 8 + tig * 2]);
            acc[mt][nt][0] = bv.x; acc[mt][nt][1] = bv.y;
            acc[mt][nt][2] = bv.x; acc[mt][nt][3] = bv.y;
        }
    mma_tiles<7, 4, 68>(sA, sW, sW + 64 * 68, acc, wm, wn * 32, gid, tig);
#pragma unroll
    for (int mt = 0; mt < 2; mt++)
#pragma unroll
        for (int nt = 0; nt < 4; nt++) {
            int row = wm * 32 + mt * 16 + gid;
            int col = wn * 32 + nt * 8 + tig * 2;
            int n = n0 + row;
            if (n < NN)
                *reinterpret_cast<float2*>(&g_h[(size_t)n * 64 + col]) =
                    make_float2(acc[mt][nt][0], acc[mt][nt][1]);
            if (n + 8 < NN)
                *reinterpret_cast<float2*>(&g_h[(size_t)(n + 8) * 64 + col]) =
                    make_float2(acc[mt][nt][2], acc[mt][nt][3]);
        }
}

// ------------------------------------------------------------------ edge embedding (coalesced staging)
__global__ __launch_bounds__(256) void k_embed_edges_mma(const float* ea, const float* b) {
    extern __shared__ float dynf[];
    float*    flat = dynf;                               // 128*41 = 5248 floats
    unsigned* sA   = reinterpret_cast<unsigned*>(dynf + 5248);   // 128*36
    unsigned* sW   = sA + 128 * 36;                      // 2 * 64*36
    int tid = threadIdx.x, e0 = blockIdx.x * 128;
    int warp = tid >> 5, lane = tid & 31;
    int wm = warp >> 1, wn = warp & 1;
    int gid = lane >> 2, tig = lane & 3;

    {
        const uint4* src = reinterpret_cast<const uint4*>(g_wbond[0]);
        uint4* dst = reinterpret_cast<uint4*>(sW);
        for (int idx = tid; idx < 2 * 64 * 36 / 4; idx += 256) dst[idx] = src[idx];
    }
    int valid = EE - e0; if (valid > 128) valid = 128;
    int nload = valid * 41;
    for (int idx = tid; idx < nload; idx += 256)
        flat[idx] = ea[(size_t)e0 * 41 + idx];           // fully coalesced stream
    __syncthreads();
    for (int idx = tid; idx < 128 * 24; idx += 256) {
        int er = idx / 24, kw = idx - er * 24;
        int k = kw * 2;
        float v0 = 0.f, v1 = 0.f;
        if (er < valid) {
            if (k < 41)     v0 = flat[er * 41 + k];
            if (k + 1 < 41) v1 = flat[er * 41 + k + 1];
        }
        sA[er * 36 + kw] = pack2(v0, v1);
    }
    __syncthreads();

    float acc[2][4][4];
#pragma unroll
    for (int mt = 0; mt < 2; mt++)
#pragma unroll
        for (int nt = 0; nt < 4; nt++) {
            float2 bv = *reinterpret_cast<const float2*>(&b[wn * 32 + nt * 8 + tig * 2]);
            acc[mt][nt][0] = bv.x; acc[mt][nt][1] = bv.y;
            acc[mt][nt][2] = bv.x; acc[mt][nt][3] = bv.y;
        }
    mma_tiles<3, 4, 36>(sA, sW, sW + 64 * 36, acc, wm, wn * 32, gid, tig);
#pragma unroll
    for (int mt = 0; mt < 2; mt++)
#pragma unroll
        for (int nt = 0; nt < 4; nt++) {
            int row = wm * 32 + mt * 16 + gid;
            int cw = wn * 16 + nt * 4 + tig;
            int e = e0 + row;
            if (e < EE)     g_ea[(size_t)e * 32 + cw]       = pack2(acc[mt][nt][0], acc[mt][nt][1]);
            if (e + 8 < EE) g_ea[(size_t)(e + 8) * 32 + cw] = pack2(acc[mt][nt][2], acc[mt][nt][3]);
        }
}

// ------------------------------------------------------------------ fused precompute (Ar|Ac|Br -> bf16)
__global__ __launch_bounds__(256) void k_precompute(int layer) {
    extern __shared__ unsigned dyn[];
    unsigned* sA = dyn;
    unsigned* sW = dyn + 128 * 36;
    int tid = threadIdx.x, n0 = blockIdx.x * 128;
    int warp = tid >> 5, lane = tid & 31;
    int wm = warp >> 1, wn = warp & 1;
    int gid = lane >> 2, tig = lane & 3;
    if (blockIdx.x == 0 && tid < 128) g_stats[tid] = 0.0;

    {
        const uint4* src = reinterpret_cast<const uint4*>(g_wpre[layer][0]);
        uint4* dst = reinterpret_cast<uint4*>(sW);
        for (int idx = tid; idx < 2 * 192 * 36 / 4; idx += 256) dst[idx] = src[idx];
    }
    for (int idx = tid; idx < 128 * 32; idx += 256) {
        int nr = idx >> 5, cw = idx & 31;
        int n = n0 + nr;
        if (n < NN) {
            float2 v = *reinterpret_cast<const float2*>(&g_h[(size_t)n * 64 + cw * 2]);
            sA[nr * 36 + cw] = pack2(v.x, v.y);
            *reinterpret_cast<float2*>(&g_hnew[(size_t)n * 64 + cw * 2]) = make_float2(0.f, 0.f);
        } else sA[nr * 36 + cw] = 0u;
    }
    __syncthreads();

    float acc[2][12][4];
#pragma unroll
    for (int mt = 0; mt < 2; mt++)
#pragma unroll
        for (int nt = 0; nt < 12; nt++) {
            int nc = wn * 96 + nt * 8 + tig * 2;
            float2 bv = *reinterpret_cast<const float2*>(&g_bpre[layer][nc]);
            acc[mt][nt][0] = bv.x; acc[mt][nt][1] = bv.y;
            acc[mt][nt][2] = bv.x; acc[mt][nt][3] = bv.y;
        }
    mma_tiles<4, 12, 36>(sA, sW, sW + 192 * 36, acc, wm, wn * 96, gid, tig);
#pragma unroll
    for (int mt = 0; mt < 2; mt++)
#pragma unroll
        for (int nt = 0; nt < 12; nt++) {
            int nc = wn * 96 + nt * 8 + tig * 2;
            unsigned* O = nc < 64 ? g_Arh : (nc < 128 ? g_Ach : g_Brh);
            int cw = (nc & 63) >> 1;
            int row = wm * 32 + mt * 16 + gid;
            int n = n0 + row;
            if (n < NN)     O[(size_t)n * 32 + cw]       = pack2(acc[mt][nt][0], acc[mt][nt][1]);
            if (n + 8 < NN) O[(size_t)(n + 8) * 32 + cw] = pack2(acc[mt][nt][2], acc[mt][nt][3]);
        }
}

// ------------------------------------------------------------------ fused edge pipeline (R7 config, bf16 gathers)
__global__ __launch_bounds__(256, 2) void k_edge(const int* eidx, int layer,
                                                 const float* b2, const float* b4,
                                                 int store_ea) {
    extern __shared__ unsigned dyn[];
    unsigned* sA = dyn;                    // 128*36
    unsigned* sW = dyn + 128 * 36;         // 4 stages * (hi 2304 + lo 2304)
    __shared__ float sB2[64], sB4[64];
    __shared__ int sRow[128], sCol[128];

    int tid = threadIdx.x;
    int warp = tid >> 5, lane = tid & 31;
    int wm = warp >> 1, wn = warp & 1;
    int gid = lane >> 2, tig = lane & 3;

    if (tid < 64) { sB2[tid] = b2[tid]; sB4[tid] = b4[tid]; }
    {
        const uint4* src = reinterpret_cast<const uint4*>(&g_wedge[layer][0][0][0]);
        uint4* dst = reinterpret_cast<uint4*>(sW);
        for (int idx = tid; idx < 4 * 2 * 2304 / 4; idx += 256) dst[idx] = src[idx];
    }
    const unsigned* W1h = sW;
    const unsigned* W2h = sW + 4608;
    const unsigned* W3h = sW + 9216;
    const unsigned* W4h = sW + 13824;

    for (int t = blockIdx.x; t < NT_EDGE; t += gridDim.x) {
        int e0 = t * 128;
        __syncthreads();                       // prior tile fully consumed
        if (tid < 128) {
            int e = e0 + tid; if (e >= EE) e = EE - 1;
            sRow[tid] = clampi(eidx[e], NN);
            sCol[tid] = clampi(eidx[EE + e], NN);
        }
        for (int idx = tid; idx < 128 * 32; idx += 256) {
            int er = idx >> 5, cw = idx & 31;
            int e = e0 + er; if (e >= EE) e = EE - 1;
            sA[er * 36 + cw] = g_ea[(size_t)e * 32 + cw];
        }
        __syncthreads();

        float acc[2][4][4];

        // ---- stage 1: t = sp(sA @ W1c + Ar[row] + Ac[col])
#pragma unroll
        for (int mt = 0; mt < 2; mt++)
#pragma unroll
            for (int nt = 0; nt < 4; nt++) {
                int row = wm * 32 + mt * 16 + gid;
                int cw = wn * 16 + nt * 4 + tig;
                float2 a0 = up2(g_Arh[(size_t)sRow[row] * 32 + cw]);
                float2 q0 = up2(g_Ach[(size_t)sCol[row] * 32 + cw]);
                float2 a1 = up2(g_Arh[(size_t)sRow[row + 8] * 32 + cw]);
                float2 q1 = up2(g_Ach[(size_t)sCol[row + 8] * 32 + cw]);
                acc[mt][nt][0] = a0.x + q0.x; acc[mt][nt][1] = a0.y + q0.y;
                acc[mt][nt][2] = a1.x + q1.x; acc[mt][nt][3] = a1.y + q1.y;
            }
        mma_tiles<4, 4, 36>(sA, W1h, W1h + 2304, acc, wm, wn * 32, gid, tig);
        __syncthreads();
#pragma unroll
        for (int mt = 0; mt < 2; mt++)
#pragma unroll
            for (int nt = 0; nt < 4; nt++) {
                int row = wm * 32 + mt * 16 + gid;
                int cw = wn * 16 + nt * 4 + tig;
                sA[row * 36 + cw]       = pack2(sp_f(acc[mt][nt][0]), sp_f(acc[mt][nt][1]));
                sA[(row + 8) * 36 + cw] = pack2(sp_f(acc[mt][nt][2]), sp_f(acc[mt][nt][3]));
            }
        __syncthreads();

        // ---- stage 2: ea_new = sA @ W2 + b2
#pragma unroll
        for (int mt = 0; mt < 2; mt++)
#pragma unroll
            for (int nt = 0; nt < 4; nt++) {
                int col = wn * 32 + nt * 8 + tig * 2;
                float2 bv = *reinterpret_cast<const float2*>(&sB2[col]);
                acc[mt][nt][0] = bv.x; acc[mt][nt][1] = bv.y;
                acc[mt][nt][2] = bv.x; acc[mt][nt][3] = bv.y;
            }
        mma_tiles<4, 4, 36>(sA, W2h, W2h + 2304, acc, wm, wn * 32, gid, tig);
        __syncthreads();
#pragma unroll
        for (int mt = 0; mt < 2; mt++)
#pragma unroll
            for (int nt = 0; nt < 4; nt++) {
                int row = wm * 32 + mt * 16 + gid;
                int cw = wn * 16 + nt * 4 + tig;
                unsigned p0 = pack2(acc[mt][nt][0], acc[mt][nt][1]);
                unsigned p1 = pack2(acc[mt][nt][2], acc[mt][nt][3]);
                sA[row * 36 + cw]       = p0;
                sA[(row + 8) * 36 + cw] = p1;
                if (store_ea) {
                    int e = e0 + row;
                    if (e < EE)     g_ea[(size_t)e * 32 + cw]       = p0;
                    if (e + 8 < EE) g_ea[(size_t)(e + 8) * 32 + cw] = p1;
                }
            }
        __syncthreads();

        // ---- stage 3: u = sp(sA @ W3 + Br[row])
#pragma unroll
        for (int mt = 0; mt < 2; mt++)
#pragma unroll
            for (int nt = 0; nt < 4; nt++) {
                int row = wm * 32 + mt * 16 + gid;
                int cw = wn * 16 + nt * 4 + tig;
                float2 v0 = up2(g_Brh[(size_t)sRow[row] * 32 + cw]);
                float2 v1 = up2(g_Brh[(size_t)sRow[row + 8] * 32 + cw]);
                acc[mt][nt][0] = v0.x; acc[mt][nt][1] = v0.y;
                acc[mt][nt][2] = v1.x; acc[mt][nt][3] = v1.y;
            }
        mma_tiles<4, 4, 36>(sA, W3h, W3h + 2304, acc, wm, wn * 32, gid, tig);
        __syncthreads();
#pragma unroll
        for (int mt = 0; mt < 2; mt++)
#pragma unroll
            for (int nt = 0; nt < 4; nt++) {
                int row = wm * 32 + mt * 16 + gid;
                int cw = wn * 16 + nt * 4 + tig;
                sA[row * 36 + cw]       = pack2(sp_f(acc[mt][nt][0]), sp_f(acc[mt][nt][1]));
                sA[(row + 8) * 36 + cw] = pack2(sp_f(acc[mt][nt][2]), sp_f(acc[mt][nt][3]));
            }
        __syncthreads();

        // ---- stage 4: msg = sA @ W4 + b4 -> vector red scatter
#pragma unroll
        for (int mt = 0; mt < 2; mt++)
#pragma unroll
            for (int nt = 0; nt < 4; nt++) {
                int col = wn * 32 + nt * 8 + tig * 2;
                float2 bv = *reinterpret_cast<const float2*>(&sB4[col]);
                acc[mt][nt][0] = bv.x; acc[mt][nt][1] = bv.y;
                acc[mt][nt][2] = bv.x; acc[mt][nt][3] = bv.y;
            }
        mma_tiles<4, 4, 36>(sA, W4h, W4h + 2304, acc, wm, wn * 32, gid, tig);
#pragma unroll
        for (int mt = 0; mt < 2; mt++)
#pragma unroll
            for (int nt = 0; nt < 4; nt++) {
                int row = wm * 32 + mt * 16 + gid;
                int col = wn * 32 + nt * 8 + tig * 2;
                int e = e0 + row;
                if (e < EE)
                    red2(&g_hnew[(size_t)sCol[row] * 64 + col], acc[mt][nt][0], acc[mt][nt][1]);
                if (e + 8 < EE)
                    red2(&g_hnew[(size_t)sCol[row + 8] * 64 + col], acc[mt][nt][2], acc[mt][nt][3]);
            }
    }
}

// ------------------------------------------------------------------ tail kernels
__global__ void k_stats() {
    int c = threadIdx.x & 63, rr = threadIdx.x >> 6;
    double s = 0.0, s2 = 0.0;
    for (int n = blockIdx.x * 4 + rr; n < NN; n += gridDim.x * 4) {
        float v = g_hnew[n * 64 + c];
        s += v; s2 += (double)v * v;
    }
    __shared__ double sh[8][64];
    sh[rr][c] = s; sh[4 + rr][c] = s2;
    __syncthreads();
    if (rr == 0) {
        atomicAdd(&g_stats[c],      sh[0][c] + sh[1][c] + sh[2][c] + sh[3][c]);
        atomicAdd(&g_stats[64 + c], sh[4][c] + sh[5][c] + sh[6][c] + sh[7][c]);
    }
}

__global__ void k_finalize(const float* gamma, const float* beta) {
    int j = threadIdx.x;
    double mu = g_stats[j] / (double)NN;
    double var = g_stats[64 + j] / (double)NN - mu * mu;
    float a = rsqrtf((float)var + 1e-5f) * gamma[j];
    g_ab[j] = a;
    g_ab[64 + j] = beta[j] - (float)mu * a;
}

// BN-apply + softplus + residual; on last layer also fused global mean pool
__global__ void k_update(const int* batch, int do_pool) {
    int idx = blockIdx.x * 256 + threadIdx.x;
    int j = idx & 63;
    float v = g_hnew[idx] * g_ab[j] + g_ab[64 + j];
    float h = sp_f(v) + g_h[idx];
    g_h[idx] = h;
    if (do_pool) {
        int b = clampi(batch[idx >> 6], GG);
        atomicAdd(&g_pool[b * 64 + j], h);
        if (j == 0) atomicAdd(&g_cnt[b], 1.f);
    }
}

__global__ void k_predict(const float* W1, const float* b1,
                          const float* W2, const float* b2,
                          const float* W3, const float* b3, float* out) {
    __shared__ float gr[64], z1[128], z2[128];
    __shared__ float red[4];
    int g = blockIdx.x, t = threadIdx.x;
    if (t < 64) gr[t] = g_pool[g * 64 + t] / fmaxf(g_cnt[g], 1.f);
    __syncthreads();
    float acc = b1[t];
    for (int k = 0; k < 64; k++) acc = fmaf(gr[k], W1[k * 128 + t], acc);
    z1[t] = sp_f(acc);
    __syncthreads();
    acc = b2[t];
    for (int k = 0; k < 128; k++) acc = fmaf(z1[k], W2[k * 128 + t], acc);
    z2[t] = sp_f(acc);
    __syncthreads();
    float v = z2[t] * W3[t];
    for (int o = 16; o > 0; o >>= 1) v += __shfl_down_sync(0xffffffff, v, o);
    if ((t & 31) == 0) red[t >> 5] = v;
    __syncthreads();
    if (t == 0) out[g] = red[0] + red[1] + red[2] + red[3] + b3[0];
}

// ------------------------------------------------------------------ launch
extern "C" void kernel_launch(void* const* d_in, const int* in_sizes, int n_in,
                              void* d_out, int out_size) {
    const float* x         = (const float*)d_in[0];
    const float* edge_attr = (const float*)d_in[1];
    const float* charge    = (const float*)d_in[2];
    const int*   eidx      = (const int*)d_in[3];
    const int*   batch     = (const int*)d_in[4];
    const float* W_charge  = (const float*)d_in[5];
    const float* b_charge  = (const float*)d_in[6];
    const float* W_atom    = (const float*)d_in[7];
    const float* b_atom    = (const float*)d_in[8];
    const float* W_bond    = (const float*)d_in[9];
    const float* b_bond    = (const float*)d_in[10];
    const float* nu_W1     = (const float*)d_in[11];
    const float* nu_b1     = (const float*)d_in[12];
    const float* nu_W2     = (const float*)d_in[13];
    const float* nu_b2     = (const float*)d_in[14];
    const float* eu_W1     = (const float*)d_in[15];
    const float* eu_b1     = (const float*)d_in[16];
    const float* eu_W2     = (const float*)d_in[17];
    const float* eu_b2     = (const float*)d_in[18];
    const float* bn_g      = (const float*)d_in[19];
    const float* bn_b      = (const float*)d_in[20];
    const float* p_W1      = (const float*)d_in[21];
    const float* p_b1      = (const float*)d_in[22];
    const float* p_W2      = (const float*)d_in[23];
    const float* p_b2      = (const float*)d_in[24];
    const float* p_W3      = (const float*)d_in[25];
    const float* p_b3      = (const float*)d_in[26];
    float* out = (float*)d_out;

    const int PRE_SMEM  = (128 * 36 + 2 * 192 * 36) * 4;   // 73728
    const int EDGE_SMEM = (128 * 36 + 4 * 2 * 2304) * 4;   // 92160
    const int EN_SMEM   = (128 * 68 + 2 * 64 * 68) * 4;    // 69632
    const int EB_SMEM   = (5248 + 128 * 36 + 2 * 64 * 36) * 4;  // 57856
    cudaFuncSetAttribute(k_precompute, cudaFuncAttributeMaxDynamicSharedMemorySize, PRE_SMEM);
    cudaFuncSetAttribute(k_edge, cudaFuncAttributeMaxDynamicSharedMemorySize, EDGE_SMEM);
    cudaFuncSetAttribute(k_embed_nodes_mma, cudaFuncAttributeMaxDynamicSharedMemorySize, EN_SMEM);
    cudaFuncSetAttribute(k_embed_edges_mma, cudaFuncAttributeMaxDynamicSharedMemorySize, EB_SMEM);

    k_charge<<<64, 256>>>(charge, W_charge, b_charge);
    k_cvt_all<<<23, 256>>>(eu_W1, eu_b1, nu_W1, nu_b1, eu_W2, nu_W2, W_bond, W_atom);
    k_embed_nodes_mma<<<(NN + 127) / 128, 256, EN_SMEM>>>(x, batch, b_atom);
    k_embed_edges_mma<<<NT_EDGE, 256, EB_SMEM>>>(edge_attr, b_bond);

    for (int i = 0; i < LL; i++) {
        k_precompute<<<(NN + 127) / 128, 256, PRE_SMEM>>>(i);
        k_edge<<<296, 256, EDGE_SMEM>>>(eidx, i, eu_b2 + i * 64, nu_b2 + i * 64,
                                        i < LL - 1 ? 1 : 0);
        k_stats<<<256, 256>>>();
        k_finalize<<<1, 64>>>(bn_g + i * 64, bn_b + i * 64);
        k_update<<<(NN * DD) / 256, 256>>>(batch, i == LL - 1 ? 1 : 0);
    }

    k_predict<<<GG, 128>>>(p_W1, p_b1, p_W2, p_b2, p_W3, p_b3, out);
}

// round 12
// speedup vs baseline: 1.3928x; 1.1744x over previous
#include <cuda_runtime.h>
#include <cuda_bf16.h>
#include <math.h>

#define NN 50000
#define EE 500000
#define GG 256
#define DD 64
#define LL 3
#define NT_EDGE ((EE + 127) / 128)

// ------------------------------------------------------------------ globals
__device__ float    g_h[NN * DD];
__device__ unsigned g_ea[(size_t)EE * 32];      // bf16x2 words
__device__ unsigned g_Arh[NN * 32];             // bf16x2 gather tables
__device__ unsigned g_Ach[NN * 32];
__device__ unsigned g_Brh[NN * 32];
__device__ float    g_hnew[NN * DD];
__device__ double   g_stats[2 * DD];
__device__ float    g_ab[2 * DD];
__device__ float    g_pool[GG * DD];
__device__ float    g_cnt[GG];
__device__ float    g_cf[GG * 16];

__device__ unsigned g_wbond[2][64 * 36];
__device__ unsigned g_wpre[LL][2][192 * 36];
__device__ unsigned g_wehi[LL][4][64 * 36];     // hi-only edge weights
__device__ unsigned g_watom[2][64 * 68];
__device__ float    g_bpre[LL][192];

__device__ __forceinline__ float sp_f(float x) {
    return x > 15.f ? x : __logf(1.f + __expf(x));
}
__device__ __forceinline__ int clampi(int v, int hi) {
    return v < 0 ? 0 : (v >= hi ? hi - 1 : v);
}
__device__ __forceinline__ unsigned pack2(float x, float y) {
    __nv_bfloat162 h = __floats2bfloat162_rn(x, y);
    return *reinterpret_cast<unsigned*>(&h);
}
__device__ __forceinline__ float2 up2(unsigned u) {
    __nv_bfloat162 h = *reinterpret_cast<__nv_bfloat162*>(&u);
    return __bfloat1622float2(h);
}
__device__ __forceinline__ void red2(float* a, float x, float y) {
    asm volatile("red.global.add.v2.f32 [%0], {%1,%2};" :: "l"(a), "f"(x), "f"(y) : "memory");
}
__device__ __forceinline__ void mma_bf16(float& c0, float& c1, float& c2, float& c3,
                                         unsigned a0, unsigned a1, unsigned a2, unsigned a3,
                                         unsigned b0, unsigned b1) {
    asm volatile("mma.sync.aligned.m16n8k16.row.col.f32.bf16.bf16.f32 "
                 "{%0,%1,%2,%3}, {%4,%5,%6,%7}, {%8,%9}, {%0,%1,%2,%3};\n"
                 : "+f"(c0), "+f"(c1), "+f"(c2), "+f"(c3)
                 : "r"(a0), "r"(a1), "r"(a2), "r"(a3), "r"(b0), "r"(b1));
}

// hi+lo split-weight version
template<int K0, int NT, int LD>
__device__ __forceinline__ void mma_tiles(const unsigned* sA, const unsigned* sWhi,
                                          const unsigned* sWlo, float acc[][NT][4],
                                          int wm, int wcol0, int gid, int tig) {
#pragma unroll
    for (int k0 = 0; k0 < K0; k0++) {
        unsigned a[2][4];
#pragma unroll
        for (int mt = 0; mt < 2; mt++) {
            const unsigned* base = &sA[(wm * 32 + mt * 16 + gid) * LD + k0 * 8 + tig];
            a[mt][0] = base[0];
            a[mt][1] = base[8 * LD];
            a[mt][2] = base[4];
            a[mt][3] = base[8 * LD + 4];
        }
#pragma unroll
        for (int nt = 0; nt < NT; nt++) {
            int off = (wcol0 + nt * 8 + gid) * LD + k0 * 8 + tig;
            unsigned bh0 = sWhi[off], bh1 = sWhi[off + 4];
            unsigned bl0 = sWlo[off], bl1 = sWlo[off + 4];
#pragma unroll
            for (int mt = 0; mt < 2; mt++) {
                mma_bf16(acc[mt][nt][0], acc[mt][nt][1], acc[mt][nt][2], acc[mt][nt][3],
                         a[mt][0], a[mt][1], a[mt][2], a[mt][3], bh0, bh1);
                mma_bf16(acc[mt][nt][0], acc[mt][nt][1], acc[mt][nt][2], acc[mt][nt][3],
                         a[mt][0], a[mt][1], a[mt][2], a[mt][3], bl0, bl1);
            }
        }
    }
}

// hi-only version (k_edge)
template<int K0, int NT, int LD>
__device__ __forceinline__ void mma_tiles_hi(const unsigned* sA, const unsigned* sWhi,
                                             float acc[][NT][4],
                                             int wm, int wcol0, int gid, int tig) {
#pragma unroll
    for (int k0 = 0; k0 < K0; k0++) {
        unsigned a[2][4];
#pragma unroll
        for (int mt = 0; mt < 2; mt++) {
            const unsigned* base = &sA[(wm * 32 + mt * 16 + gid) * LD + k0 * 8 + tig];
            a[mt][0] = base[0];
            a[mt][1] = base[8 * LD];
            a[mt][2] = base[4];
            a[mt][3] = base[8 * LD + 4];
        }
#pragma unroll
        for (int nt = 0; nt < NT; nt++) {
            int off = (wcol0 + nt * 8 + gid) * LD + k0 * 8 + tig;
            unsigned bh0 = sWhi[off], bh1 = sWhi[off + 4];
#pragma unroll
            for (int mt = 0; mt < 2; mt++)
                mma_bf16(acc[mt][nt][0], acc[mt][nt][1], acc[mt][nt][2], acc[mt][nt][3],
                         a[mt][0], a[mt][1], a[mt][2], a[mt][3], bh0, bh1);
        }
    }
}

// ------------------------------------------------------------------ one-time weight conversion
__global__ void k_cvt_all(const float* eu_W1, const float* eu_b1,
                          const float* nu_W1, const float* nu_b1,
                          const float* eu_W2, const float* nu_W2,
                          const float* W_bond, const float* W_atom) {
    int b = blockIdx.x, tid = threadIdx.x;
    if (b == 22) {   // W_atom
        __nv_bfloat16* hhi = reinterpret_cast<__nv_bfloat16*>(g_watom[0]);
        __nv_bfloat16* hlo = reinterpret_cast<__nv_bfloat16*>(g_watom[1]);
        for (int idx = tid; idx < 112 * 64; idx += 256) {
            int k = idx >> 6, n = idx & 63;
            float w = (k < 108) ? W_atom[k * 64 + n] : 0.f;
            __nv_bfloat16 hi = __float2bfloat16(w);
            float lo = w - __bfloat162float(hi);
            hhi[(size_t)n * 136 + k] = hi;
            hlo[(size_t)n * 136 + k] = __float2bfloat16(lo);
        }
        return;
    }
    const float* src; int j = -1, i = 0, ncoff = 0, validK = 64;
    unsigned *dhi = 0, *dlo = 0;
    if (b == 0) {
        src = W_bond; validK = 41;
        dhi = g_wbond[0]; dlo = g_wbond[1];
        for (int idx = tid; idx < LL * 192; idx += 256) {
            int ii = idx / 192, n = idx % 192;
            float v = 0.f;
            if (n < 64)        v = eu_b1[ii * 64 + n];
            else if (n >= 128) v = nu_b1[ii * 64 + (n - 128)];
            g_bpre[ii][n] = v;
        }
    } else {
        i = (b - 1) / 7; j = (b - 1) % 7;
        const float* euW1 = eu_W1 + (size_t)i * 12288;
        const float* nuW1 = nu_W1 + (size_t)i * 8192;
        switch (j) {
            case 0: src = euW1;            dhi = g_wpre[i][0]; dlo = g_wpre[i][1]; ncoff = 0;   break;
            case 1: src = euW1 + 4096;     dhi = g_wpre[i][0]; dlo = g_wpre[i][1]; ncoff = 64;  break;
            case 2: src = nuW1;            dhi = g_wpre[i][0]; dlo = g_wpre[i][1]; ncoff = 128; break;
            case 3: src = euW1 + 8192;     dhi = g_wehi[i][0]; break;
            case 4: src = eu_W2 + (size_t)i * 4096; dhi = g_wehi[i][1]; break;
            case 5: src = nuW1 + 4096;     dhi = g_wehi[i][2]; break;
            default: src = nu_W2 + (size_t)i * 4096; dhi = g_wehi[i][3]; break;
        }
    }
    __nv_bfloat16* hhi = reinterpret_cast<__nv_bfloat16*>(dhi);
    __nv_bfloat16* hlo = reinterpret_cast<__nv_bfloat16*>(dlo);
    for (int idx = tid; idx < 4096; idx += 256) {
        int k = idx >> 6, n = idx & 63;
        float w = (k < validK) ? src[k * 64 + n] : 0.f;
        __nv_bfloat16 hi = __float2bfloat16(w);
        hhi[(size_t)(n + ncoff) * 72 + k] = hi;
        if (hlo) {
            float lo = w - __bfloat162float(hi);
            hlo[(size_t)(n + ncoff) * 72 + k] = __float2bfloat16(lo);
        }
    }
}

// ------------------------------------------------------------------ small kernels
__global__ void k_charge(const float* charge, const float* Wc, const float* bc) {
    int i = blockIdx.x * 256 + threadIdx.x;
    if (i < GG * 16) g_cf[i] = charge[i >> 4] * Wc[i & 15] + bc[i & 15];
    if (i < GG * DD) g_pool[i] = 0.f;
    if (i < GG) g_cnt[i] = 0.f;
}

// ------------------------------------------------------------------ node embedding via MMA (K=112)
__global__ __launch_bounds__(256) void k_embed_nodes_mma(
    const float* x, const int* batch, const float* b) {
    extern __shared__ unsigned dyn[];
    unsigned* sA = dyn;
    unsigned* sW = dyn + 128 * 68;
    int tid = threadIdx.x, n0 = blockIdx.x * 128;
    int warp = tid >> 5, lane = tid & 31;
    int wm = warp >> 1, wn = warp & 1;
    int gid = lane >> 2, tig = lane & 3;

    {
        const uint4* src = reinterpret_cast<const uint4*>(g_watom[0]);
        uint4* dst = reinterpret_cast<uint4*>(sW);
        for (int idx = tid; idx < 2 * 64 * 68 / 4; idx += 256) dst[idx] = src[idx];
    }
    for (int idx = tid; idx < 128 * 56; idx += 256) {
        int nr = idx / 56, kw = idx - nr * 56;
        int n = n0 + nr; if (n >= NN) n = NN - 1;
        int k = kw * 2;
        float v0, v1;
        int bb = clampi(batch[n], GG);
        v0 = (k < 92)      ? x[(size_t)n * 92 + k]
           : (k < 108)     ? g_cf[bb * 16 + (k - 92)] : 0.f;
        int k1 = k + 1;
        v1 = (k1 < 92)     ? x[(size_t)n * 92 + k1]
           : (k1 < 108)    ? g_cf[bb * 16 + (k1 - 92)] : 0.f;
        sA[nr * 68 + kw] = pack2(v0, v1);
    }
    __syncthreads();

    float acc[2][4][4];
#pragma unroll
    for (int mt = 0; mt < 2; mt++)
#pragma unroll
        for (int nt = 0; nt < 4; nt++) {
            float2 bv = *reinterpret_cast<const float2*>(&b[wn * 32 + nt * 8 + tig * 2]);
            acc[mt][nt][0] = bv.x; acc[mt][nt][1] = bv.y;
            acc[mt][nt][2] = bv.x; acc[mt][nt][3] = bv.y;
        }
    mma_tiles<7, 4, 68>(sA, sW, sW + 64 * 68, acc, wm, wn * 32, gid, tig);
#pragma unroll
    for (int mt = 0; mt < 2; mt++)
#pragma unroll
        for (int nt = 0; nt < 4; nt++) {
            int row = wm * 32 + mt * 16 + gid;
            int col = wn * 32 + nt * 8 + tig * 2;
            int n = n0 + row;
            if (n < NN)
                *reinterpret_cast<float2*>(&g_h[(size_t)n * 64 + col]) =
                    make_float2(acc[mt][nt][0], acc[mt][nt][1]);
            if (n + 8 < NN)
                *reinterpret_cast<float2*>(&g_h[(size_t)(n + 8) * 64 + col]) =
                    make_float2(acc[mt][nt][2], acc[mt][nt][3]);
        }
}

// ------------------------------------------------------------------ edge embedding (coalesced staging)
__global__ __launch_bounds__(256) void k_embed_edges_mma(const float* ea, const float* b) {
    extern __shared__ float dynf[];
    float*    flat = dynf;
    unsigned* sA   = reinterpret_cast<unsigned*>(dynf + 5248);
    unsigned* sW   = sA + 128 * 36;
    int tid = threadIdx.x, e0 = blockIdx.x * 128;
    int warp = tid >> 5, lane = tid & 31;
    int wm = warp >> 1, wn = warp & 1;
    int gid = lane >> 2, tig = lane & 3;

    {
        const uint4* src = reinterpret_cast<const uint4*>(g_wbond[0]);
        uint4* dst = reinterpret_cast<uint4*>(sW);
        for (int idx = tid; idx < 2 * 64 * 36 / 4; idx += 256) dst[idx] = src[idx];
    }
    int valid = EE - e0; if (valid > 128) valid = 128;
    int nload = valid * 41;
    for (int idx = tid; idx < nload; idx += 256)
        flat[idx] = ea[(size_t)e0 * 41 + idx];
    __syncthreads();
    for (int idx = tid; idx < 128 * 24; idx += 256) {
        int er = idx / 24, kw = idx - er * 24;
        int k = kw * 2;
        float v0 = 0.f, v1 = 0.f;
        if (er < valid) {
            if (k < 41)     v0 = flat[er * 41 + k];
            if (k + 1 < 41) v1 = flat[er * 41 + k + 1];
        }
        sA[er * 36 + kw] = pack2(v0, v1);
    }
    __syncthreads();

    float acc[2][4][4];
#pragma unroll
    for (int mt = 0; mt < 2; mt++)
#pragma unroll
        for (int nt = 0; nt < 4; nt++) {
            float2 bv = *reinterpret_cast<const float2*>(&b[wn * 32 + nt * 8 + tig * 2]);
            acc[mt][nt][0] = bv.x; acc[mt][nt][1] = bv.y;
            acc[mt][nt][2] = bv.x; acc[mt][nt][3] = bv.y;
        }
    mma_tiles<3, 4, 36>(sA, sW, sW + 64 * 36, acc, wm, wn * 32, gid, tig);
#pragma unroll
    for (int mt = 0; mt < 2; mt++)
#pragma unroll
        for (int nt = 0; nt < 4; nt++) {
            int row = wm * 32 + mt * 16 + gid;
            int cw = wn * 16 + nt * 4 + tig;
            int e = e0 + row;
            if (e < EE)     g_ea[(size_t)e * 32 + cw]       = pack2(acc[mt][nt][0], acc[mt][nt][1]);
            if (e + 8 < EE) g_ea[(size_t)(e + 8) * 32 + cw] = pack2(acc[mt][nt][2], acc[mt][nt][3]);
        }
}

// ------------------------------------------------------------------ fused precompute (Ar|Ac|Br -> bf16)
__global__ __launch_bounds__(256) void k_precompute(int layer) {
    extern __shared__ unsigned dyn[];
    unsigned* sA = dyn;
    unsigned* sW = dyn + 128 * 36;
    int tid = threadIdx.x, n0 = blockIdx.x * 128;
    int warp = tid >> 5, lane = tid & 31;
    int wm = warp >> 1, wn = warp & 1;
    int gid = lane >> 2, tig = lane & 3;
    if (blockIdx.x == 0 && tid < 128) g_stats[tid] = 0.0;

    {
        const uint4* src = reinterpret_cast<const uint4*>(g_wpre[layer][0]);
        uint4* dst = reinterpret_cast<uint4*>(sW);
        for (int idx = tid; idx < 2 * 192 * 36 / 4; idx += 256) dst[idx] = src[idx];
    }
    for (int idx = tid; idx < 128 * 32; idx += 256) {
        int nr = idx >> 5, cw = idx & 31;
        int n = n0 + nr;
        if (n < NN) {
            float2 v = *reinterpret_cast<const float2*>(&g_h[(size_t)n * 64 + cw * 2]);
            sA[nr * 36 + cw] = pack2(v.x, v.y);
            *reinterpret_cast<float2*>(&g_hnew[(size_t)n * 64 + cw * 2]) = make_float2(0.f, 0.f);
        } else sA[nr * 36 + cw] = 0u;
    }
    __syncthreads();

    float acc[2][12][4];
#pragma unroll
    for (int mt = 0; mt < 2; mt++)
#pragma unroll
        for (int nt = 0; nt < 12; nt++) {
            int nc = wn * 96 + nt * 8 + tig * 2;
            float2 bv = *reinterpret_cast<const float2*>(&g_bpre[layer][nc]);
            acc[mt][nt][0] = bv.x; acc[mt][nt][1] = bv.y;
            acc[mt][nt][2] = bv.x; acc[mt][nt][3] = bv.y;
        }
    mma_tiles<4, 12, 36>(sA, sW, sW + 192 * 36, acc, wm, wn * 96, gid, tig);
#pragma unroll
    for (int mt = 0; mt < 2; mt++)
#pragma unroll
        for (int nt = 0; nt < 12; nt++) {
            int nc = wn * 96 + nt * 8 + tig * 2;
            unsigned* O = nc < 64 ? g_Arh : (nc < 128 ? g_Ach : g_Brh);
            int cw = (nc & 63) >> 1;
            int row = wm * 32 + mt * 16 + gid;
            int n = n0 + row;
            if (n < NN)     O[(size_t)n * 32 + cw]       = pack2(acc[mt][nt][0], acc[mt][nt][1]);
            if (n + 8 < NN) O[(size_t)(n + 8) * 32 + cw] = pack2(acc[mt][nt][2], acc[mt][nt][3]);
        }
}

// ------------------------------------------------------------------ fused edge pipeline (hi-only weights, 3 CTA/SM)
__global__ __launch_bounds__(256, 3) void k_edge(const int* eidx, int layer,
                                                 const float* b2, const float* b4,
                                                 int store_ea) {
    extern __shared__ unsigned dyn[];
    unsigned* sA = dyn;                    // 128*36
    unsigned* sW = dyn + 128 * 36;         // 4 stages * 2304 (hi only)
    __shared__ float sB2[64], sB4[64];
    __shared__ int sRow[128], sCol[128];

    int tid = threadIdx.x;
    int warp = tid >> 5, lane = tid & 31;
    int wm = warp >> 1, wn = warp & 1;
    int gid = lane >> 2, tig = lane & 3;

    if (tid < 64) { sB2[tid] = b2[tid]; sB4[tid] = b4[tid]; }
    {
        const uint4* src = reinterpret_cast<const uint4*>(&g_wehi[layer][0][0]);
        uint4* dst = reinterpret_cast<uint4*>(sW);
        for (int idx = tid; idx < 4 * 2304 / 4; idx += 256) dst[idx] = src[idx];
    }
    const unsigned* W1h = sW;
    const unsigned* W2h = sW + 2304;
    const unsigned* W3h = sW + 4608;
    const unsigned* W4h = sW + 6912;

    for (int t = blockIdx.x; t < NT_EDGE; t += gridDim.x) {
        int e0 = t * 128;
        __syncthreads();                       // prior tile fully consumed
        if (tid < 128) {
            int e = e0 + tid; if (e >= EE) e = EE - 1;
            sRow[tid] = clampi(eidx[e], NN);
            sCol[tid] = clampi(eidx[EE + e], NN);
        }
        for (int idx = tid; idx < 128 * 32; idx += 256) {
            int er = idx >> 5, cw = idx & 31;
            int e = e0 + er; if (e >= EE) e = EE - 1;
            sA[er * 36 + cw] = g_ea[(size_t)e * 32 + cw];
        }
        __syncthreads();

        float acc[2][4][4];

        // ---- stage 1: t = sp(sA @ W1c + Ar[row] + Ac[col])
#pragma unroll
        for (int mt = 0; mt < 2; mt++)
#pragma unroll
            for (int nt = 0; nt < 4; nt++) {
                int row = wm * 32 + mt * 16 + gid;
                int cw = wn * 16 + nt * 4 + tig;
                float2 a0 = up2(g_Arh[(size_t)sRow[row] * 32 + cw]);
                float2 q0 = up2(g_Ach[(size_t)sCol[row] * 32 + cw]);
                float2 a1 = up2(g_Arh[(size_t)sRow[row + 8] * 32 + cw]);
                float2 q1 = up2(g_Ach[(size_t)sCol[row + 8] * 32 + cw]);
                acc[mt][nt][0] = a0.x + q0.x; acc[mt][nt][1] = a0.y + q0.y;
                acc[mt][nt][2] = a1.x + q1.x; acc[mt][nt][3] = a1.y + q1.y;
            }
        mma_tiles_hi<4, 4, 36>(sA, W1h, acc, wm, wn * 32, gid, tig);
        __syncthreads();
#pragma unroll
        for (int mt = 0; mt < 2; mt++)
#pragma unroll
            for (int nt = 0; nt < 4; nt++) {
                int row = wm * 32 + mt * 16 + gid;
                int cw = wn * 16 + nt * 4 + tig;
                sA[row * 36 + cw]       = pack2(sp_f(acc[mt][nt][0]), sp_f(acc[mt][nt][1]));
                sA[(row + 8) * 36 + cw] = pack2(sp_f(acc[mt][nt][2]), sp_f(acc[mt][nt][3]));
            }
        __syncthreads();

        // ---- stage 2: ea_new = sA @ W2 + b2
#pragma unroll
        for (int mt = 0; mt < 2; mt++)
#pragma unroll
            for (int nt = 0; nt < 4; nt++) {
                int col = wn * 32 + nt * 8 + tig * 2;
                float2 bv = *reinterpret_cast<const float2*>(&sB2[col]);
                acc[mt][nt][0] = bv.x; acc[mt][nt][1] = bv.y;
                acc[mt][nt][2] = bv.x; acc[mt][nt][3] = bv.y;
            }
        mma_tiles_hi<4, 4, 36>(sA, W2h, acc, wm, wn * 32, gid, tig);
        __syncthreads();
#pragma unroll
        for (int mt = 0; mt < 2; mt++)
#pragma unroll
            for (int nt = 0; nt < 4; nt++) {
                int row = wm * 32 + mt * 16 + gid;
                int cw = wn * 16 + nt * 4 + tig;
                unsigned p0 = pack2(acc[mt][nt][0], acc[mt][nt][1]);
                unsigned p1 = pack2(acc[mt][nt][2], acc[mt][nt][3]);
                sA[row * 36 + cw]       = p0;
                sA[(row + 8) * 36 + cw] = p1;
                if (store_ea) {
                    int e = e0 + row;
                    if (e < EE)     g_ea[(size_t)e * 32 + cw]       = p0;
                    if (e + 8 < EE) g_ea[(size_t)(e + 8) * 32 + cw] = p1;
                }
            }
        __syncthreads();

        // ---- stage 3: u = sp(sA @ W3 + Br[row])
#pragma unroll
        for (int mt = 0; mt < 2; mt++)
#pragma unroll
            for (int nt = 0; nt < 4; nt++) {
                int row = wm * 32 + mt * 16 + gid;
                int cw = wn * 16 + nt * 4 + tig;
                float2 v0 = up2(g_Brh[(size_t)sRow[row] * 32 + cw]);
                float2 v1 = up2(g_Brh[(size_t)sRow[row + 8] * 32 + cw]);
                acc[mt][nt][0] = v0.x; acc[mt][nt][1] = v0.y;
                acc[mt][nt][2] = v1.x; acc[mt][nt][3] = v1.y;
            }
        mma_tiles_hi<4, 4, 36>(sA, W3h, acc, wm, wn * 32, gid, tig);
        __syncthreads();
#pragma unroll
        for (int mt = 0; mt < 2; mt++)
#pragma unroll
            for (int nt = 0; nt < 4; nt++) {
                int row = wm * 32 + mt * 16 + gid;
                int cw = wn * 16 + nt * 4 + tig;
                sA[row * 36 + cw]       = pack2(sp_f(acc[mt][nt][0]), sp_f(acc[mt][nt][1]));
                sA[(row + 8) * 36 + cw] = pack2(sp_f(acc[mt][nt][2]), sp_f(acc[mt][nt][3]));
            }
        __syncthreads();

        // ---- stage 4: msg = sA @ W4 + b4 -> vector red scatter
#pragma unroll
        for (int mt = 0; mt < 2; mt++)
#pragma unroll
            for (int nt = 0; nt < 4; nt++) {
                int col = wn * 32 + nt * 8 + tig * 2;
                float2 bv = *reinterpret_cast<const float2*>(&sB4[col]);
                acc[mt][nt][0] = bv.x; acc[mt][nt][1] = bv.y;
                acc[mt][nt][2] = bv.x; acc[mt][nt][3] = bv.y;
            }
        mma_tiles_hi<4, 4, 36>(sA, W4h, acc, wm, wn * 32, gid, tig);
#pragma unroll
        for (int mt = 0; mt < 2; mt++)
#pragma unroll
            for (int nt = 0; nt < 4; nt++) {
                int row = wm * 32 + mt * 16 + gid;
                int col = wn * 32 + nt * 8 + tig * 2;
                int e = e0 + row;
                if (e < EE)
                    red2(&g_hnew[(size_t)sCol[row] * 64 + col], acc[mt][nt][0], acc[mt][nt][1]);
                if (e + 8 < EE)
                    red2(&g_hnew[(size_t)sCol[row + 8] * 64 + col], acc[mt][nt][2], acc[mt][nt][3]);
            }
    }
}

// ------------------------------------------------------------------ tail kernels
__global__ void k_stats() {
    int c = threadIdx.x & 63, rr = threadIdx.x >> 6;
    double s = 0.0, s2 = 0.0;
    for (int n = blockIdx.x * 4 + rr; n < NN; n += gridDim.x * 4) {
        float v = g_hnew[n * 64 + c];
        s += v; s2 += (double)v * v;
    }
    __shared__ double sh[8][64];
    sh[rr][c] = s; sh[4 + rr][c] = s2;
    __syncthreads();
    if (rr == 0) {
        atomicAdd(&g_stats[c],      sh[0][c] + sh[1][c] + sh[2][c] + sh[3][c]);
        atomicAdd(&g_stats[64 + c], sh[4][c] + sh[5][c] + sh[6][c] + sh[7][c]);
    }
}

__global__ void k_finalize(const float* gamma, const float* beta) {
    int j = threadIdx.x;
    double mu = g_stats[j] / (double)NN;
    double var = g_stats[64 + j] / (double)NN - mu * mu;
    float a = rsqrtf((float)var + 1e-5f) * gamma[j];
    g_ab[j] = a;
    g_ab[64 + j] = beta[j] - (float)mu * a;
}

__global__ void k_update(const int* batch, int do_pool) {
    int idx = blockIdx.x * 256 + threadIdx.x;
    int j = idx & 63;
    float v = g_hnew[idx] * g_ab[j] + g_ab[64 + j];
    float h = sp_f(v) + g_h[idx];
    g_h[idx] = h;
    if (do_pool) {
        int b = clampi(batch[idx >> 6], GG);
        atomicAdd(&g_pool[b * 64 + j], h);
        if (j == 0) atomicAdd(&g_cnt[b], 1.f);
    }
}

__global__ void k_predict(const float* W1, const float* b1,
                          const float* W2, const float* b2,
                          const float* W3, const float* b3, float* out) {
    __shared__ float gr[64], z1[128], z2[128];
    __shared__ float red[4];
    int g = blockIdx.x, t = threadIdx.x;
    if (t < 64) gr[t] = g_pool[g * 64 + t] / fmaxf(g_cnt[g], 1.f);
    __syncthreads();
    float acc = b1[t];
    for (int k = 0; k < 64; k++) acc = fmaf(gr[k], W1[k * 128 + t], acc);
    z1[t] = sp_f(acc);
    __syncthreads();
    acc = b2[t];
    for (int k = 0; k < 128; k++) acc = fmaf(z1[k], W2[k * 128 + t], acc);
    z2[t] = sp_f(acc);
    __syncthreads();
    float v = z2[t] * W3[t];
    for (int o = 16; o > 0; o >>= 1) v += __shfl_down_sync(0xffffffff, v, o);
    if ((t & 31) == 0) red[t >> 5] = v;
    __syncthreads();
    if (t == 0) out[g] = red[0] + red[1] + red[2] + red[3] + b3[0];
}

// ------------------------------------------------------------------ launch
extern "C" void kernel_launch(void* const* d_in, const int* in_sizes, int n_in,
                              void* d_out, int out_size) {
    const float* x         = (const float*)d_in[0];
    const float* edge_attr = (const float*)d_in[1];
    const float* charge    = (const float*)d_in[2];
    const int*   eidx      = (const int*)d_in[3];
    const int*   batch     = (const int*)d_in[4];
    const float* W_charge  = (const float*)d_in[5];
    const float* b_charge  = (const float*)d_in[6];
    const float* W_atom    = (const float*)d_in[7];
    const float* b_atom    = (const float*)d_in[8];
    const float* W_bond    = (const float*)d_in[9];
    const float* b_bond    = (const float*)d_in[10];
    const float* nu_W1     = (const float*)d_in[11];
    const float* nu_b1     = (const float*)d_in[12];
    const float* nu_W2     = (const float*)d_in[13];
    const float* nu_b2     = (const float*)d_in[14];
    const float* eu_W1     = (const float*)d_in[15];
    const float* eu_b1     = (const float*)d_in[16];
    const float* eu_W2     = (const float*)d_in[17];
    const float* eu_b2     = (const float*)d_in[18];
    const float* bn_g      = (const float*)d_in[19];
    const float* bn_b      = (const float*)d_in[20];
    const float* p_W1      = (const float*)d_in[21];
    const float* p_b1      = (const float*)d_in[22];
    const float* p_W2      = (const float*)d_in[23];
    const float* p_b2      = (const float*)d_in[24];
    const float* p_W3      = (const float*)d_in[25];
    const float* p_b3      = (const float*)d_in[26];
    float* out = (float*)d_out;

    const int PRE_SMEM  = (128 * 36 + 2 * 192 * 36) * 4;       // 73728
    const int EDGE_SMEM = (128 * 36 + 4 * 2304) * 4;           // 55296
    const int EN_SMEM   = (128 * 68 + 2 * 64 * 68) * 4;        // 69632
    const int EB_SMEM   = (5248 + 128 * 36 + 2 * 64 * 36) * 4; // 57856
    cudaFuncSetAttribute(k_precompute, cudaFuncAttributeMaxDynamicSharedMemorySize, PRE_SMEM);
    cudaFuncSetAttribute(k_edge, cudaFuncAttributeMaxDynamicSharedMemorySize, EDGE_SMEM);
    cudaFuncSetAttribute(k_embed_nodes_mma, cudaFuncAttributeMaxDynamicSharedMemorySize, EN_SMEM);
    cudaFuncSetAttribute(k_embed_edges_mma, cudaFuncAttributeMaxDynamicSharedMemorySize, EB_SMEM);

    k_charge<<<64, 256>>>(charge, W_charge, b_charge);
    k_cvt_all<<<23, 256>>>(eu_W1, eu_b1, nu_W1, nu_b1, eu_W2, nu_W2, W_bond, W_atom);
    k_embed_nodes_mma<<<(NN + 127) / 128, 256, EN_SMEM>>>(x, batch, b_atom);
    k_embed_edges_mma<<<NT_EDGE, 256, EB_SMEM>>>(edge_attr, b_bond);

    for (int i = 0; i < LL; i++) {
        k_precompute<<<(NN + 127) / 128, 256, PRE_SMEM>>>(i);
        k_edge<<<444, 256, EDGE_SMEM>>>(eidx, i, eu_b2 + i * 64, nu_b2 + i * 64,
                                        i < LL - 1 ? 1 : 0);
        k_stats<<<256, 256>>>();
        k_finalize<<<1, 64>>>(bn_g + i * 64, bn_b + i * 64);
        k_update<<<(NN * DD) / 256, 256>>>(batch, i == LL - 1 ? 1 : 0);
    }

    k_predict<<<GG, 128>>>(p_W1, p_b1, p_W2, p_b2, p_W3, p_b3, out);
}

// round 13
// speedup vs baseline: 1.4521x; 1.0426x over previous
#include <cuda_runtime.h>
#include <cuda_bf16.h>
#include <math.h>

#define NN 50000
#define EE 500000
#define GG 256
#define DD 64
#define LL 3
#define NT_EDGE ((EE + 127) / 128)

// ------------------------------------------------------------------ globals
__device__ float    g_h[NN * DD];
__device__ unsigned g_ea[(size_t)EE * 32];      // bf16x2 words
__device__ unsigned g_Arh[NN * 32];             // bf16x2 gather tables
__device__ unsigned g_Ach[NN * 32];
__device__ unsigned g_Brh[NN * 32];
__device__ float    g_hnew[NN * DD];
__device__ double   g_stats[2 * DD];
__device__ float    g_ab[2 * DD];
__device__ float    g_pool[GG * DD];
__device__ float    g_cnt[GG];
__device__ float    g_cf[GG * 16];

__device__ unsigned g_wbond[64 * 36];           // hi-only
__device__ unsigned g_wpre[LL][192 * 36];       // hi-only
__device__ unsigned g_wehi[LL][4][64 * 36];     // hi-only
__device__ unsigned g_watom[2][64 * 68];        // hi+lo (fp32 output path)
__device__ float    g_bpre[LL][192];

__device__ __forceinline__ float sp_f(float x) {
    return x > 15.f ? x : __logf(1.f + __expf(x));
}
__device__ __forceinline__ int clampi(int v, int hi) {
    return v < 0 ? 0 : (v >= hi ? hi - 1 : v);
}
__device__ __forceinline__ unsigned pack2(float x, float y) {
    __nv_bfloat162 h = __floats2bfloat162_rn(x, y);
    return *reinterpret_cast<unsigned*>(&h);
}
__device__ __forceinline__ float2 up2(unsigned u) {
    __nv_bfloat162 h = *reinterpret_cast<__nv_bfloat162*>(&u);
    return __bfloat1622float2(h);
}
__device__ __forceinline__ void red2(float* a, float x, float y) {
    asm volatile("red.global.add.v2.f32 [%0], {%1,%2};" :: "l"(a), "f"(x), "f"(y) : "memory");
}
__device__ __forceinline__ void mma_bf16(float& c0, float& c1, float& c2, float& c3,
                                         unsigned a0, unsigned a1, unsigned a2, unsigned a3,
                                         unsigned b0, unsigned b1) {
    asm volatile("mma.sync.aligned.m16n8k16.row.col.f32.bf16.bf16.f32 "
                 "{%0,%1,%2,%3}, {%4,%5,%6,%7}, {%8,%9}, {%0,%1,%2,%3};\n"
                 : "+f"(c0), "+f"(c1), "+f"(c2), "+f"(c3)
                 : "r"(a0), "r"(a1), "r"(a2), "r"(a3), "r"(b0), "r"(b1));
}

// hi+lo split-weight version (embed_nodes only)
template<int K0, int NT, int LD>
__device__ __forceinline__ void mma_tiles(const unsigned* sA, const unsigned* sWhi,
                                          const unsigned* sWlo, float acc[][NT][4],
                                          int wm, int wcol0, int gid, int tig) {
#pragma unroll
    for (int k0 = 0; k0 < K0; k0++) {
        unsigned a[2][4];
#pragma unroll
        for (int mt = 0; mt < 2; mt++) {
            const unsigned* base = &sA[(wm * 32 + mt * 16 + gid) * LD + k0 * 8 + tig];
            a[mt][0] = base[0];
            a[mt][1] = base[8 * LD];
            a[mt][2] = base[4];
            a[mt][3] = base[8 * LD + 4];
        }
#pragma unroll
        for (int nt = 0; nt < NT; nt++) {
            int off = (wcol0 + nt * 8 + gid) * LD + k0 * 8 + tig;
            unsigned bh0 = sWhi[off], bh1 = sWhi[off + 4];
            unsigned bl0 = sWlo[off], bl1 = sWlo[off + 4];
#pragma unroll
            for (int mt = 0; mt < 2; mt++) {
                mma_bf16(acc[mt][nt][0], acc[mt][nt][1], acc[mt][nt][2], acc[mt][nt][3],
                         a[mt][0], a[mt][1], a[mt][2], a[mt][3], bh0, bh1);
                mma_bf16(acc[mt][nt][0], acc[mt][nt][1], acc[mt][nt][2], acc[mt][nt][3],
                         a[mt][0], a[mt][1], a[mt][2], a[mt][3], bl0, bl1);
            }
        }
    }
}

// hi-only version
template<int K0, int NT, int LD>
__device__ __forceinline__ void mma_tiles_hi(const unsigned* sA, const unsigned* sWhi,
                                             float acc[][NT][4],
                                             int wm, int wcol0, int gid, int tig) {
#pragma unroll
    for (int k0 = 0; k0 < K0; k0++) {
        unsigned a[2][4];
#pragma unroll
        for (int mt = 0; mt < 2; mt++) {
            const unsigned* base = &sA[(wm * 32 + mt * 16 + gid) * LD + k0 * 8 + tig];
            a[mt][0] = base[0];
            a[mt][1] = base[8 * LD];
            a[mt][2] = base[4];
            a[mt][3] = base[8 * LD + 4];
        }
#pragma unroll
        for (int nt = 0; nt < NT; nt++) {
            int off = (wcol0 + nt * 8 + gid) * LD + k0 * 8 + tig;
            unsigned bh0 = sWhi[off], bh1 = sWhi[off + 4];
#pragma unroll
            for (int mt = 0; mt < 2; mt++)
                mma_bf16(acc[mt][nt][0], acc[mt][nt][1], acc[mt][nt][2], acc[mt][nt][3],
                         a[mt][0], a[mt][1], a[mt][2], a[mt][3], bh0, bh1);
        }
    }
}

// ------------------------------------------------------------------ one-time weight conversion
__global__ void k_cvt_all(const float* eu_W1, const float* eu_b1,
                          const float* nu_W1, const float* nu_b1,
                          const float* eu_W2, const float* nu_W2,
                          const float* W_bond, const float* W_atom) {
    int b = blockIdx.x, tid = threadIdx.x;
    if (b == 22) {   // W_atom: hi+lo
        __nv_bfloat16* hhi = reinterpret_cast<__nv_bfloat16*>(g_watom[0]);
        __nv_bfloat16* hlo = reinterpret_cast<__nv_bfloat16*>(g_watom[1]);
        for (int idx = tid; idx < 112 * 64; idx += 256) {
            int k = idx >> 6, n = idx & 63;
            float w = (k < 108) ? W_atom[k * 64 + n] : 0.f;
            __nv_bfloat16 hi = __float2bfloat16(w);
            float lo = w - __bfloat162float(hi);
            hhi[(size_t)n * 136 + k] = hi;
            hlo[(size_t)n * 136 + k] = __float2bfloat16(lo);
        }
        return;
    }
    const float* src; int i = 0, ncoff = 0, validK = 64;
    unsigned* dhi = 0;
    if (b == 0) {
        src = W_bond; validK = 41;
        dhi = g_wbond;
        for (int idx = tid; idx < LL * 192; idx += 256) {
            int ii = idx / 192, n = idx % 192;
            float v = 0.f;
            if (n < 64)        v = eu_b1[ii * 64 + n];
            else if (n >= 128) v = nu_b1[ii * 64 + (n - 128)];
            g_bpre[ii][n] = v;
        }
    } else {
        i = (b - 1) / 7; int j = (b - 1) % 7;
        const float* euW1 = eu_W1 + (size_t)i * 12288;
        const float* nuW1 = nu_W1 + (size_t)i * 8192;
        switch (j) {
            case 0: src = euW1;            dhi = g_wpre[i]; ncoff = 0;   break;
            case 1: src = euW1 + 4096;     dhi = g_wpre[i]; ncoff = 64;  break;
            case 2: src = nuW1;            dhi = g_wpre[i]; ncoff = 128; break;
            case 3: src = euW1 + 8192;     dhi = g_wehi[i][0]; break;
            case 4: src = eu_W2 + (size_t)i * 4096; dhi = g_wehi[i][1]; break;
            case 5: src = nuW1 + 4096;     dhi = g_wehi[i][2]; break;
            default: src = nu_W2 + (size_t)i * 4096; dhi = g_wehi[i][3]; break;
        }
    }
    __nv_bfloat16* hhi = reinterpret_cast<__nv_bfloat16*>(dhi);
    for (int idx = tid; idx < 4096; idx += 256) {
        int k = idx >> 6, n = idx & 63;
        float w = (k < validK) ? src[k * 64 + n] : 0.f;
        hhi[(size_t)(n + ncoff) * 72 + k] = __float2bfloat16(w);
    }
}

// ------------------------------------------------------------------ small kernels
__global__ void k_charge(const float* charge, const float* Wc, const float* bc) {
    int i = blockIdx.x * 256 + threadIdx.x;
    if (i < GG * 16) g_cf[i] = charge[i >> 4] * Wc[i & 15] + bc[i & 15];
    if (i < GG * DD) g_pool[i] = 0.f;
    if (i < GG) g_cnt[i] = 0.f;
}

// ------------------------------------------------------------------ node embedding via MMA (K=112)
__global__ __launch_bounds__(256) void k_embed_nodes_mma(
    const float* x, const int* batch, const float* b) {
    extern __shared__ unsigned dyn[];
    unsigned* sA = dyn;
    unsigned* sW = dyn + 128 * 68;
    int tid = threadIdx.x, n0 = blockIdx.x * 128;
    int warp = tid >> 5, lane = tid & 31;
    int wm = warp >> 1, wn = warp & 1;
    int gid = lane >> 2, tig = lane & 3;

    {
        const uint4* src = reinterpret_cast<const uint4*>(g_watom[0]);
        uint4* dst = reinterpret_cast<uint4*>(sW);
        for (int idx = tid; idx < 2 * 64 * 68 / 4; idx += 256) dst[idx] = src[idx];
    }
    for (int idx = tid; idx < 128 * 56; idx += 256) {
        int nr = idx / 56, kw = idx - nr * 56;
        int n = n0 + nr; if (n >= NN) n = NN - 1;
        int k = kw * 2;
        float v0, v1;
        int bb = clampi(batch[n], GG);
        v0 = (k < 92)      ? x[(size_t)n * 92 + k]
           : (k < 108)     ? g_cf[bb * 16 + (k - 92)] : 0.f;
        int k1 = k + 1;
        v1 = (k1 < 92)     ? x[(size_t)n * 92 + k1]
           : (k1 < 108)    ? g_cf[bb * 16 + (k1 - 92)] : 0.f;
        sA[nr * 68 + kw] = pack2(v0, v1);
    }
    __syncthreads();

    float acc[2][4][4];
#pragma unroll
    for (int mt = 0; mt < 2; mt++)
#pragma unroll
        for (int nt = 0; nt < 4; nt++) {
            float2 bv = *reinterpret_cast<const float2*>(&b[wn * 32 + nt * 8 + tig * 2]);
            acc[mt][nt][0] = bv.x; acc[mt][nt][1] = bv.y;
            acc[mt][nt][2] = bv.x; acc[mt][nt][3] = bv.y;
        }
    mma_tiles<7, 4, 68>(sA, sW, sW + 64 * 68, acc, wm, wn * 32, gid, tig);
#pragma unroll
    for (int mt = 0; mt < 2; mt++)
#pragma unroll
        for (int nt = 0; nt < 4; nt++) {
            int row = wm * 32 + mt * 16 + gid;
            int col = wn * 32 + nt * 8 + tig * 2;
            int n = n0 + row;
            if (n < NN)
                *reinterpret_cast<float2*>(&g_h[(size_t)n * 64 + col]) =
                    make_float2(acc[mt][nt][0], acc[mt][nt][1]);
            if (n + 8 < NN)
                *reinterpret_cast<float2*>(&g_h[(size_t)(n + 8) * 64 + col]) =
                    make_float2(acc[mt][nt][2], acc[mt][nt][3]);
        }
}

// ------------------------------------------------------------------ edge embedding (hi-only)
__global__ __launch_bounds__(256) void k_embed_edges_mma(const float* ea, const float* b) {
    extern __shared__ float dynf[];
    float*    flat = dynf;                               // 128*41
    unsigned* sA   = reinterpret_cast<unsigned*>(dynf + 5248);
    unsigned* sW   = sA + 128 * 36;                      // 64*36 hi only
    int tid = threadIdx.x, e0 = blockIdx.x * 128;
    int warp = tid >> 5, lane = tid & 31;
    int wm = warp >> 1, wn = warp & 1;
    int gid = lane >> 2, tig = lane & 3;

    {
        const uint4* src = reinterpret_cast<const uint4*>(g_wbond);
        uint4* dst = reinterpret_cast<uint4*>(sW);
        for (int idx = tid; idx < 64 * 36 / 4; idx += 256) dst[idx] = src[idx];
    }
    int valid = EE - e0; if (valid > 128) valid = 128;
    int nload = valid * 41;
    for (int idx = tid; idx < nload; idx += 256)
        flat[idx] = ea[(size_t)e0 * 41 + idx];
    __syncthreads();
    for (int idx = tid; idx < 128 * 24; idx += 256) {
        int er = idx / 24, kw = idx - er * 24;
        int k = kw * 2;
        float v0 = 0.f, v1 = 0.f;
        if (er < valid) {
            if (k < 41)     v0 = flat[er * 41 + k];
            if (k + 1 < 41) v1 = flat[er * 41 + k + 1];
        }
        sA[er * 36 + kw] = pack2(v0, v1);
    }
    __syncthreads();

    float acc[2][4][4];
#pragma unroll
    for (int mt = 0; mt < 2; mt++)
#pragma unroll
        for (int nt = 0; nt < 4; nt++) {
            float2 bv = *reinterpret_cast<const float2*>(&b[wn * 32 + nt * 8 + tig * 2]);
            acc[mt][nt][0] = bv.x; acc[mt][nt][1] = bv.y;
            acc[mt][nt][2] = bv.x; acc[mt][nt][3] = bv.y;
        }
    mma_tiles_hi<3, 4, 36>(sA, sW, acc, wm, wn * 32, gid, tig);
#pragma unroll
    for (int mt = 0; mt < 2; mt++)
#pragma unroll
        for (int nt = 0; nt < 4; nt++) {
            int row = wm * 32 + mt * 16 + gid;
            int cw = wn * 16 + nt * 4 + tig;
            int e = e0 + row;
            if (e < EE)     g_ea[(size_t)e * 32 + cw]       = pack2(acc[mt][nt][0], acc[mt][nt][1]);
            if (e + 8 < EE) g_ea[(size_t)(e + 8) * 32 + cw] = pack2(acc[mt][nt][2], acc[mt][nt][3]);
        }
}

// ------------------------------------------------------------------ fused precompute (+ BN/update of previous layer)
// do_update==0: read g_h directly (first layer).
// do_update==1: h = sp(g_hnew*a + b) + g_h; write g_h; use h. (fuses k_update)
__global__ __launch_bounds__(256) void k_precompute(int layer, int do_update) {
    extern __shared__ unsigned dyn[];
    unsigned* sA = dyn;                       // 128*36
    unsigned* sW = dyn + 128 * 36;            // 192*36 hi only
    int tid = threadIdx.x, n0 = blockIdx.x * 128;
    int warp = tid >> 5, lane = tid & 31;
    int wm = warp >> 1, wn = warp & 1;
    int gid = lane >> 2, tig = lane & 3;
    if (blockIdx.x == 0 && tid < 128) g_stats[tid] = 0.0;

    {
        const uint4* src = reinterpret_cast<const uint4*>(g_wpre[layer]);
        uint4* dst = reinterpret_cast<uint4*>(sW);
        for (int idx = tid; idx < 192 * 36 / 4; idx += 256) dst[idx] = src[idx];
    }
    for (int idx = tid; idx < 128 * 32; idx += 256) {
        int nr = idx >> 5, cw = idx & 31;
        int n = n0 + nr;
        if (n < NN) {
            size_t off = (size_t)n * 64 + cw * 2;
            float2 h = *reinterpret_cast<const float2*>(&g_h[off]);
            if (do_update) {
                float2 hn = *reinterpret_cast<const float2*>(&g_hnew[off]);
                int j = cw * 2;
                h.x = sp_f(hn.x * g_ab[j]     + g_ab[64 + j])     + h.x;
                h.y = sp_f(hn.y * g_ab[j + 1] + g_ab[64 + j + 1]) + h.y;
                *reinterpret_cast<float2*>(&g_h[off]) = h;
            }
            sA[nr * 36 + cw] = pack2(h.x, h.y);
            *reinterpret_cast<float2*>(&g_hnew[off]) = make_float2(0.f, 0.f);
        } else sA[nr * 36 + cw] = 0u;
    }
    __syncthreads();

    float acc[2][12][4];
#pragma unroll
    for (int mt = 0; mt < 2; mt++)
#pragma unroll
        for (int nt = 0; nt < 12; nt++) {
            int nc = wn * 96 + nt * 8 + tig * 2;
            float2 bv = *reinterpret_cast<const float2*>(&g_bpre[layer][nc]);
            acc[mt][nt][0] = bv.x; acc[mt][nt][1] = bv.y;
            acc[mt][nt][2] = bv.x; acc[mt][nt][3] = bv.y;
        }
    mma_tiles_hi<4, 12, 36>(sA, sW, acc, wm, wn * 96, gid, tig);
#pragma unroll
    for (int mt = 0; mt < 2; mt++)
#pragma unroll
        for (int nt = 0; nt < 12; nt++) {
            int nc = wn * 96 + nt * 8 + tig * 2;
            unsigned* O = nc < 64 ? g_Arh : (nc < 128 ? g_Ach : g_Brh);
            int cw = (nc & 63) >> 1;
            int row = wm * 32 + mt * 16 + gid;
            int n = n0 + row;
            if (n < NN)     O[(size_t)n * 32 + cw]       = pack2(acc[mt][nt][0], acc[mt][nt][1]);
            if (n + 8 < NN) O[(size_t)(n + 8) * 32 + cw] = pack2(acc[mt][nt][2], acc[mt][nt][3]);
        }
}

// ------------------------------------------------------------------ fused edge pipeline (hi-only weights, 3 CTA/SM)
__global__ __launch_bounds__(256, 3) void k_edge(const int* eidx, int layer,
                                                 const float* b2, const float* b4,
                                                 int store_ea) {
    extern __shared__ unsigned dyn[];
    unsigned* sA = dyn;                    // 128*36
    unsigned* sW = dyn + 128 * 36;         // 4 stages * 2304
    __shared__ float sB2[64], sB4[64];
    __shared__ int sRow[128], sCol[128];

    int tid = threadIdx.x;
    int warp = tid >> 5, lane = tid & 31;
    int wm = warp >> 1, wn = warp & 1;
    int gid = lane >> 2, tig = lane & 3;

    if (tid < 64) { sB2[tid] = b2[tid]; sB4[tid] = b4[tid]; }
    {
        const uint4* src = reinterpret_cast<const uint4*>(&g_wehi[layer][0][0]);
        uint4* dst = reinterpret_cast<uint4*>(sW);
        for (int idx = tid; idx < 4 * 2304 / 4; idx += 256) dst[idx] = src[idx];
    }
    const unsigned* W1h = sW;
    const unsigned* W2h = sW + 2304;
    const unsigned* W3h = sW + 4608;
    const unsigned* W4h = sW + 6912;

    for (int t = blockIdx.x; t < NT_EDGE; t += gridDim.x) {
        int e0 = t * 128;
        __syncthreads();
        if (tid < 128) {
            int e = e0 + tid; if (e >= EE) e = EE - 1;
            sRow[tid] = clampi(eidx[e], NN);
            sCol[tid] = clampi(eidx[EE + e], NN);
        }
        for (int idx = tid; idx < 128 * 32; idx += 256) {
            int er = idx >> 5, cw = idx & 31;
            int e = e0 + er; if (e >= EE) e = EE - 1;
            sA[er * 36 + cw] = g_ea[(size_t)e * 32 + cw];
        }
        __syncthreads();

        float acc[2][4][4];

        // ---- stage 1
#pragma unroll
        for (int mt = 0; mt < 2; mt++)
#pragma unroll
            for (int nt = 0; nt < 4; nt++) {
                int row = wm * 32 + mt * 16 + gid;
                int cw = wn * 16 + nt * 4 + tig;
                float2 a0 = up2(g_Arh[(size_t)sRow[row] * 32 + cw]);
                float2 q0 = up2(g_Ach[(size_t)sCol[row] * 32 + cw]);
                float2 a1 = up2(g_Arh[(size_t)sRow[row + 8] * 32 + cw]);
                float2 q1 = up2(g_Ach[(size_t)sCol[row + 8] * 32 + cw]);
                acc[mt][nt][0] = a0.x + q0.x; acc[mt][nt][1] = a0.y + q0.y;
                acc[mt][nt][2] = a1.x + q1.x; acc[mt][nt][3] = a1.y + q1.y;
            }
        mma_tiles_hi<4, 4, 36>(sA, W1h, acc, wm, wn * 32, gid, tig);
        __syncthreads();
#pragma unroll
        for (int mt = 0; mt < 2; mt++)
#pragma unroll
            for (int nt = 0; nt < 4; nt++) {
                int row = wm * 32 + mt * 16 + gid;
                int cw = wn * 16 + nt * 4 + tig;
                sA[row * 36 + cw]       = pack2(sp_f(acc[mt][nt][0]), sp_f(acc[mt][nt][1]));
                sA[(row + 8) * 36 + cw] = pack2(sp_f(acc[mt][nt][2]), sp_f(acc[mt][nt][3]));
            }
        __syncthreads();

        // ---- stage 2
#pragma unroll
        for (int mt = 0; mt < 2; mt++)
#pragma unroll
            for (int nt = 0; nt < 4; nt++) {
                int col = wn * 32 + nt * 8 + tig * 2;
                float2 bv = *reinterpret_cast<const float2*>(&sB2[col]);
                acc[mt][nt][0] = bv.x; acc[mt][nt][1] = bv.y;
                acc[mt][nt][2] = bv.x; acc[mt][nt][3] = bv.y;
            }
        mma_tiles_hi<4, 4, 36>(sA, W2h, acc, wm, wn * 32, gid, tig);
        __syncthreads();
#pragma unroll
        for (int mt = 0; mt < 2; mt++)
#pragma unroll
            for (int nt = 0; nt < 4; nt++) {
                int row = wm * 32 + mt * 16 + gid;
                int cw = wn * 16 + nt * 4 + tig;
                unsigned p0 = pack2(acc[mt][nt][0], acc[mt][nt][1]);
                unsigned p1 = pack2(acc[mt][nt][2], acc[mt][nt][3]);
                sA[row * 36 + cw]       = p0;
                sA[(row + 8) * 36 + cw] = p1;
                if (store_ea) {
                    int e = e0 + row;
                    if (e < EE)     g_ea[(size_t)e * 32 + cw]       = p0;
                    if (e + 8 < EE) g_ea[(size_t)(e + 8) * 32 + cw] = p1;
                }
            }
        __syncthreads();

        // ---- stage 3
#pragma unroll
        for (int mt = 0; mt < 2; mt++)
#pragma unroll
            for (int nt = 0; nt < 4; nt++) {
                int row = wm * 32 + mt * 16 + gid;
                int cw = wn * 16 + nt * 4 + tig;
                float2 v0 = up2(g_Brh[(size_t)sRow[row] * 32 + cw]);
                float2 v1 = up2(g_Brh[(size_t)sRow[row + 8] * 32 + cw]);
                acc[mt][nt][0] = v0.x; acc[mt][nt][1] = v0.y;
                acc[mt][nt][2] = v1.x; acc[mt][nt][3] = v1.y;
            }
        mma_tiles_hi<4, 4, 36>(sA, W3h, acc, wm, wn * 32, gid, tig);
        __syncthreads();
#pragma unroll
        for (int mt = 0; mt < 2; mt++)
#pragma unroll
            for (int nt = 0; nt < 4; nt++) {
                int row = wm * 32 + mt * 16 + gid;
                int cw = wn * 16 + nt * 4 + tig;
                sA[row * 36 + cw]       = pack2(sp_f(acc[mt][nt][0]), sp_f(acc[mt][nt][1]));
                sA[(row + 8) * 36 + cw] = pack2(sp_f(acc[mt][nt][2]), sp_f(acc[mt][nt][3]));
            }
        __syncthreads();

        // ---- stage 4 -> scatter
#pragma unroll
        for (int mt = 0; mt < 2; mt++)
#pragma unroll
            for (int nt = 0; nt < 4; nt++) {
                int col = wn * 32 + nt * 8 + tig * 2;
                float2 bv = *reinterpret_cast<const float2*>(&sB4[col]);
                acc[mt][nt][0] = bv.x; acc[mt][nt][1] = bv.y;
                acc[mt][nt][2] = bv.x; acc[mt][nt][3] = bv.y;
            }
        mma_tiles_hi<4, 4, 36>(sA, W4h, acc, wm, wn * 32, gid, tig);
#pragma unroll
        for (int mt = 0; mt < 2; mt++)
#pragma unroll
            for (int nt = 0; nt < 4; nt++) {
                int row = wm * 32 + mt * 16 + gid;
                int col = wn * 32 + nt * 8 + tig * 2;
                int e = e0 + row;
                if (e < EE)
                    red2(&g_hnew[(size_t)sCol[row] * 64 + col], acc[mt][nt][0], acc[mt][nt][1]);
                if (e + 8 < EE)
                    red2(&g_hnew[(size_t)sCol[row + 8] * 64 + col], acc[mt][nt][2], acc[mt][nt][3]);
            }
    }
}

// ------------------------------------------------------------------ tail kernels
__global__ void k_stats() {
    int c = threadIdx.x & 63, rr = threadIdx.x >> 6;
    double s = 0.0, s2 = 0.0;
    for (int n = blockIdx.x * 4 + rr; n < NN; n += gridDim.x * 4) {
        float v = g_hnew[n * 64 + c];
        s += v; s2 += (double)v * v;
    }
    __shared__ double sh[8][64];
    sh[rr][c] = s; sh[4 + rr][c] = s2;
    __syncthreads();
    if (rr == 0) {
        atomicAdd(&g_stats[c],      sh[0][c] + sh[1][c] + sh[2][c] + sh[3][c]);
        atomicAdd(&g_stats[64 + c], sh[4][c] + sh[5][c] + sh[6][c] + sh[7][c]);
    }
}

__global__ void k_finalize(const float* gamma, const float* beta) {
    int j = threadIdx.x;
    double mu = g_stats[j] / (double)NN;
    double var = g_stats[64 + j] / (double)NN - mu * mu;
    float a = rsqrtf((float)var + 1e-5f) * gamma[j];
    g_ab[j] = a;
    g_ab[64 + j] = beta[j] - (float)mu * a;
}

// final layer: BN-apply + softplus + residual + fused pool
__global__ void k_update_pool(const int* batch) {
    int idx = blockIdx.x * 256 + threadIdx.x;
    int j = idx & 63;
    float v = g_hnew[idx] * g_ab[j] + g_ab[64 + j];
    float h = sp_f(v) + g_h[idx];
    int b = clampi(batch[idx >> 6], GG);
    atomicAdd(&g_pool[b * 64 + j], h);
    if (j == 0) atomicAdd(&g_cnt[b], 1.f);
}

__global__ void k_predict(const float* W1, const float* b1,
                          const float* W2, const float* b2,
                          const float* W3, const float* b3, float* out) {
    __shared__ float gr[64], z1[128], z2[128];
    __shared__ float red[4];
    int g = blockIdx.x, t = threadIdx.x;
    if (t < 64) gr[t] = g_pool[g * 64 + t] / fmaxf(g_cnt[g], 1.f);
    __syncthreads();
    float acc = b1[t];
    for (int k = 0; k < 64; k++) acc = fmaf(gr[k], W1[k * 128 + t], acc);
    z1[t] = sp_f(acc);
    __syncthreads();
    acc = b2[t];
    for (int k = 0; k < 128; k++) acc = fmaf(z1[k], W2[k * 128 + t], acc);
    z2[t] = sp_f(acc);
    __syncthreads();
    float v = z2[t] * W3[t];
    for (int o = 16; o > 0; o >>= 1) v += __shfl_down_sync(0xffffffff, v, o);
    if ((t & 31) == 0) red[t >> 5] = v;
    __syncthreads();
    if (t == 0) out[g] = red[0] + red[1] + red[2] + red[3] + b3[0];
}

// ------------------------------------------------------------------ launch
extern "C" void kernel_launch(void* const* d_in, const int* in_sizes, int n_in,
                              void* d_out, int out_size) {
    const float* x         = (const float*)d_in[0];
    const float* edge_attr = (const float*)d_in[1];
    const float* charge    = (const float*)d_in[2];
    const int*   eidx      = (const int*)d_in[3];
    const int*   batch     = (const int*)d_in[4];
    const float* W_charge  = (const float*)d_in[5];
    const float* b_charge  = (const float*)d_in[6];
    const float* W_atom    = (const float*)d_in[7];
    const float* b_atom    = (const float*)d_in[8];
    const float* W_bond    = (const float*)d_in[9];
    const float* b_bond    = (const float*)d_in[10];
    const float* nu_W1     = (const float*)d_in[11];
    const float* nu_b1     = (const float*)d_in[12];
    const float* nu_W2     = (const float*)d_in[13];
    const float* nu_b2     = (const float*)d_in[14];
    const float* eu_W1     = (const float*)d_in[15];
    const float* eu_b1     = (const float*)d_in[16];
    const float* eu_W2     = (const float*)d_in[17];
    const float* eu_b2     = (const float*)d_in[18];
    const float* bn_g      = (const float*)d_in[19];
    const float* bn_b      = (const float*)d_in[20];
    const float* p_W1      = (const float*)d_in[21];
    const float* p_b1      = (const float*)d_in[22];
    const float* p_W2      = (const float*)d_in[23];
    const float* p_b2      = (const float*)d_in[24];
    const float* p_W3      = (const float*)d_in[25];
    const float* p_b3      = (const float*)d_in[26];
    float* out = (float*)d_out;

    const int PRE_SMEM  = (128 * 36 + 192 * 36) * 4;           // 46080
    const int EDGE_SMEM = (128 * 36 + 4 * 2304) * 4;           // 55296
    const int EN_SMEM   = (128 * 68 + 2 * 64 * 68) * 4;        // 69632
    const int EB_SMEM   = (5248 + 128 * 36 + 64 * 36) * 4;     // 48640
    cudaFuncSetAttribute(k_precompute, cudaFuncAttributeMaxDynamicSharedMemorySize, PRE_SMEM);
    cudaFuncSetAttribute(k_edge, cudaFuncAttributeMaxDynamicSharedMemorySize, EDGE_SMEM);
    cudaFuncSetAttribute(k_embed_nodes_mma, cudaFuncAttributeMaxDynamicSharedMemorySize, EN_SMEM);
    cudaFuncSetAttribute(k_embed_edges_mma, cudaFuncAttributeMaxDynamicSharedMemorySize, EB_SMEM);

    k_charge<<<64, 256>>>(charge, W_charge, b_charge);
    k_cvt_all<<<23, 256>>>(eu_W1, eu_b1, nu_W1, nu_b1, eu_W2, nu_W2, W_bond, W_atom);
    k_embed_nodes_mma<<<(NN + 127) / 128, 256, EN_SMEM>>>(x, batch, b_atom);
    k_embed_edges_mma<<<NT_EDGE, 256, EB_SMEM>>>(edge_attr, b_bond);

    for (int i = 0; i < LL; i++) {
        k_precompute<<<(NN + 127) / 128, 256, PRE_SMEM>>>(i, i > 0 ? 1 : 0);
        k_edge<<<444, 256, EDGE_SMEM>>>(eidx, i, eu_b2 + i * 64, nu_b2 + i * 64,
                                        i < LL - 1 ? 1 : 0);
        k_stats<<<256, 256>>>();
        k_finalize<<<1, 64>>>(bn_g + i * 64, bn_b + i * 64);
    }
    k_update_pool<<<(NN * DD) / 256, 256>>>(batch);
    k_predict<<<GG, 128>>>(p_W1, p_b1, p_W2, p_b2, p_W3, p_b3, out);
}